// round 11
// baseline (speedup 1.0000x reference)
#include <cuda_runtime.h>
#include <cuda_bf16.h>
#include <math.h>
#include <stdint.h>

// Problem constants
#define B_ 32
#define T_ 512
#define D_ 512
#define H_ 8
#define M_ (B_ * T_)   // 16384 rows
#define F_ 2048

// ---------------------------------------------------------------------------
// Scratch (device globals; no allocation allowed)
// ---------------------------------------------------------------------------
__device__ float g_tmp[(size_t)M_ * D_];
__device__ float g_Y  [(size_t)M_ * D_];
__device__ float g_Z  [(size_t)M_ * D_];

__device__ __nv_bfloat16 g_h1  [(size_t)M_ * D_];     // X / Y split
__device__ __nv_bfloat16 g_l1  [(size_t)M_ * D_];
__device__ __nv_bfloat16 g_h2  [(size_t)M_ * D_];     // ENC / Z split
__device__ __nv_bfloat16 g_l2  [(size_t)M_ * D_];
__device__ __nv_bfloat16 g_qkvh[(size_t)M_ * 1536];   // self QKV fused
__device__ __nv_bfloat16 g_qkvl[(size_t)M_ * 1536];
__device__ __nv_bfloat16 g_kvh [(size_t)M_ * 1024];   // cross KV fused
__device__ __nv_bfloat16 g_kvl [(size_t)M_ * 1024];
__device__ __nv_bfloat16 g_q2h [(size_t)M_ * D_];     // cross Q
__device__ __nv_bfloat16 g_q2l [(size_t)M_ * D_];
__device__ __nv_bfloat16 g_ath [(size_t)M_ * D_];
__device__ __nv_bfloat16 g_atl [(size_t)M_ * D_];
__device__ __nv_bfloat16 g_Fh  [(size_t)M_ * F_];
__device__ __nv_bfloat16 g_Fl  [(size_t)M_ * F_];
__device__ __nv_bfloat16 g_Wh  [4194304];
__device__ __nv_bfloat16 g_Wl  [4194304];

// ---------------------------------------------------------------------------
// helpers
// ---------------------------------------------------------------------------
__device__ __forceinline__ uint32_t smem_u32(const void* p) {
    uint32_t a;
    asm("{ .reg .u64 t; cvta.to.shared.u64 t, %1; cvt.u32.u64 %0, t; }"
        : "=r"(a) : "l"(p));
    return a;
}

#define PDL_TRIGGER() asm volatile("griddepcontrol.launch_dependents;" ::: "memory")
#define PDL_WAIT()    asm volatile("griddepcontrol.wait;" ::: "memory")

#define CP_ASYNC16(dst, src) \
    asm volatile("cp.async.cg.shared.global [%0], [%1], 16;" :: \
                 "r"(dst), "l"(src) : "memory")
#define CP_COMMIT() asm volatile("cp.async.commit_group;" ::: "memory")
#define CP_WAIT(n)  asm volatile("cp.async.wait_group %0;" :: "n"(n) : "memory")

#define LDMATRIX_X4(r0, r1, r2, r3, addr) \
    asm volatile("ldmatrix.sync.aligned.m8n8.x4.shared.b16 {%0,%1,%2,%3}, [%4];" \
                 : "=r"(r0), "=r"(r1), "=r"(r2), "=r"(r3) : "r"(addr))

#define LDMATRIX_X4_T(r0, r1, r2, r3, addr) \
    asm volatile("ldmatrix.sync.aligned.m8n8.x4.trans.shared.b16 {%0,%1,%2,%3}, [%4];" \
                 : "=r"(r0), "=r"(r1), "=r"(r2), "=r"(r3) : "r"(addr))

#define MMA_BF16(d0, d1, d2, d3, a0, a1, a2, a3, b0, b1) \
    asm volatile("mma.sync.aligned.m16n8k16.row.col.f32.bf16.bf16.f32 " \
                 "{%0,%1,%2,%3}, {%4,%5,%6,%7}, {%8,%9}, {%0,%1,%2,%3};" \
                 : "+f"(d0), "+f"(d1), "+f"(d2), "+f"(d3) \
                 : "r"(a0), "r"(a1), "r"(a2), "r"(a3), "r"(b0), "r"(b1))

__device__ __forceinline__ void split2(float x, float y, uint32_t& hi, uint32_t& lo) {
    __nv_bfloat162 h = __floats2bfloat162_rn(x, y);
    float hx = __low2float(h), hy = __high2float(h);
    __nv_bfloat162 l = __floats2bfloat162_rn(x - hx, y - hy);
    hi = *reinterpret_cast<uint32_t*>(&h);
    lo = *reinterpret_cast<uint32_t*>(&l);
}

// ---------------------------------------------------------------------------
// merged split: 12 segments in one launch
// ---------------------------------------------------------------------------
struct SplitSegs {
    const float* src[12];
    __nv_bfloat16* hi[12];
    __nv_bfloat16* lo[12];
    int n4[12];
};

__global__ void __launch_bounds__(256)
msplit_kernel(SplitSegs s)
{
    PDL_TRIGGER();
    int i = blockIdx.x * 256 + threadIdx.x;
#pragma unroll
    for (int k = 0; k < 12; k++) {
        if (i < s.n4[k]) {
            float4 v = ((const float4*)s.src[k])[i];
            uint32_t h0, l0, h1, l1;
            split2(v.x, v.y, h0, l0);
            split2(v.z, v.w, h1, l1);
            uint32_t* hp = (uint32_t*)s.hi[k];
            uint32_t* lp = (uint32_t*)s.lo[k];
            hp[2 * i] = h0; hp[2 * i + 1] = h1;
            lp[2 * i] = l0; lp[2 * i + 1] = l1;
            return;
        }
        i -= s.n4[k];
    }
}

// ---------------------------------------------------------------------------
// HMMA GEMM body (3-pass bf16 split), CTA tile 128x256, 256 threads,
// 8 warps (2 M x 4 N), warp tile 64x64. XOR-swizzled SMEM, 3-stage cp.async.
// ldmatrix:MMA ratio 16:96 per k-slice (2x better than 64x32 warp tile);
// 255-reg budget (1 CTA) lets ptxas double-buffer fragments.
// ---------------------------------------------------------------------------
#define A_TILE_B 8192                // 128 rows x 64 B
#define B_TILE_B 16384               // 256 rows x 64 B
#define STAGE_B (2 * A_TILE_B + 2 * B_TILE_B)   // 49152
#define OFF_AL  A_TILE_B             // 8192
#define OFF_BH  (2 * A_TILE_B)       // 16384
#define OFF_BL  (2 * A_TILE_B + B_TILE_B)  // 32768
#define GEMM_SMEM (3 * STAGE_B)      // 147456

template <int BIAS, int LEAKY, int SPLIT>
__device__ __forceinline__ void gemm_body(
    const __nv_bfloat16* __restrict__ Ah, const __nv_bfloat16* __restrict__ Al,
    const __nv_bfloat16* __restrict__ Bh, const __nv_bfloat16* __restrict__ Bl,
    const float* __restrict__ bias, float* __restrict__ C,
    __nv_bfloat16* __restrict__ Chi, __nv_bfloat16* __restrict__ Clo,
    int N, int K, int bm, int bn, char* smem)
{
    PDL_TRIGGER();
    const uint32_t sbase = smem_u32(smem);

    const int tid = threadIdx.x;
    const int wid = tid >> 5, lane = tid & 31;
    const int wm = wid & 1, wn = wid >> 1;     // 2 M x 4 N warp grid

    const int ldr0 = tid >> 2;            // row 0..63
    const int ldc4 = tid & 3;             // 16B-chunk 0..3
    const int ldce = ldc4 * 8;            // element col

    const __nv_bfloat16* gAh = Ah + (size_t)(bm + ldr0) * K + ldce;
    const __nv_bfloat16* gAl = Al + (size_t)(bm + ldr0) * K + ldce;
    const __nv_bfloat16* gBh = Bh + (size_t)(bn + ldr0) * K + ldce;
    const __nv_bfloat16* gBl = Bl + (size_t)(bn + ldr0) * K + ldce;
    const size_t rstep = (size_t)64 * K;

    // swizzled store offsets: A rows ldr0, ldr0+64; B rows ldr0 + 64h
    uint32_t sro[4];
#pragma unroll
    for (int h = 0; h < 4; h++) {
        const int r = ldr0 + h * 64;
        sro[h] = (uint32_t)(r * 64 + ((ldc4 ^ ((r >> 1) & 3)) << 4));
    }

    const int aRowB = wm * 64 + (lane & 15);
    const int aKc0  = (lane >> 4);
    const int aSw   = (aRowB >> 1) & 3;
    const int bRowB = wn * 64 + (lane & 7) + ((lane >> 4) << 3);
    const int bKc0  = (lane >> 3) & 1;
    const int bSw   = (bRowB >> 1) & 3;

    float acc[4][8][4];
#pragma unroll
    for (int i = 0; i < 4; i++)
#pragma unroll
        for (int j = 0; j < 8; j++)
#pragma unroll
            for (int r = 0; r < 4; r++) acc[i][j][r] = 0.f;

    const int NC = K >> 5;

    auto load_chunk = [&](int c, int buf) {
        const uint32_t st = sbase + buf * STAGE_B;
        const int koff = c << 5;
#pragma unroll
        for (int h = 0; h < 2; h++) {
            CP_ASYNC16(st + sro[h],          gAh + (size_t)h * rstep + koff);
            CP_ASYNC16(st + OFF_AL + sro[h], gAl + (size_t)h * rstep + koff);
        }
#pragma unroll
        for (int h = 0; h < 4; h++) {
            CP_ASYNC16(st + OFF_BH + sro[h], gBh + (size_t)h * rstep + koff);
            CP_ASYNC16(st + OFF_BL + sro[h], gBl + (size_t)h * rstep + koff);
        }
        CP_COMMIT();
    };

    PDL_WAIT();
    load_chunk(0, 0);
    load_chunk(1, 1);
    int lbuf = 2, cbuf = 0;

    for (int c = 0; c < NC; c++) {
        if (c + 1 < NC) { CP_WAIT(1); } else { CP_WAIT(0); }
        __syncthreads();
        if (c + 2 < NC) {
            load_chunk(c + 2, lbuf);
            lbuf = (lbuf == 2) ? 0 : lbuf + 1;
        }

        const uint32_t st  = sbase + cbuf * STAGE_B;
        cbuf = (cbuf == 2) ? 0 : cbuf + 1;
        const uint32_t aBh = st,           aBl = st + OFF_AL;
        const uint32_t bBh = st + OFF_BH,  bBl = st + OFF_BL;

#pragma unroll
        for (int ks = 0; ks < 2; ks++) {
            const uint32_t aoff = (uint32_t)(aRowB * 64 +
                                  (((ks * 2 + aKc0) ^ aSw) << 4));
            const uint32_t boff = (uint32_t)(bRowB * 64 +
                                  (((ks * 2 + bKc0) ^ bSw) << 4));

            // B frags: 64 cols hi + lo (8 ldmatrix.x4)
            uint32_t bh[8][2], bl[8][2];
#pragma unroll
            for (int j2 = 0; j2 < 4; j2++) {
                uint32_t r0, r1, r2, r3;
                LDMATRIX_X4(r0, r1, r2, r3, bBh + boff + j2 * 1024);
                bh[j2 * 2 + 0][0] = r0; bh[j2 * 2 + 0][1] = r1;
                bh[j2 * 2 + 1][0] = r2; bh[j2 * 2 + 1][1] = r3;
                LDMATRIX_X4(r0, r1, r2, r3, bBl + boff + j2 * 1024);
                bl[j2 * 2 + 0][0] = r0; bl[j2 * 2 + 0][1] = r1;
                bl[j2 * 2 + 1][0] = r2; bl[j2 * 2 + 1][1] = r3;
            }
            // A hi frags: pass0 (Ah*Bh) + pass1 (Ah*Bl)
            uint32_t a[4][4];
#pragma unroll
            for (int i = 0; i < 4; i++)
                LDMATRIX_X4(a[i][0], a[i][1], a[i][2], a[i][3],
                            aBh + aoff + i * 1024);
#pragma unroll
            for (int i = 0; i < 4; i++)
#pragma unroll
                for (int j = 0; j < 8; j++)
                    MMA_BF16(acc[i][j][0], acc[i][j][1], acc[i][j][2], acc[i][j][3],
                             a[i][0], a[i][1], a[i][2], a[i][3], bh[j][0], bh[j][1]);
#pragma unroll
            for (int i = 0; i < 4; i++)
#pragma unroll
                for (int j = 0; j < 8; j++)
                    MMA_BF16(acc[i][j][0], acc[i][j][1], acc[i][j][2], acc[i][j][3],
                             a[i][0], a[i][1], a[i][2], a[i][3], bl[j][0], bl[j][1]);
            // A lo frags (reuse regs): pass2 (Al*Bh)
#pragma unroll
            for (int i = 0; i < 4; i++)
                LDMATRIX_X4(a[i][0], a[i][1], a[i][2], a[i][3],
                            aBl + aoff + i * 1024);
#pragma unroll
            for (int i = 0; i < 4; i++)
#pragma unroll
                for (int j = 0; j < 8; j++)
                    MMA_BF16(acc[i][j][0], acc[i][j][1], acc[i][j][2], acc[i][j][3],
                             a[i][0], a[i][1], a[i][2], a[i][3], bh[j][0], bh[j][1]);
        }
    }

    const int tg = lane >> 2;
    const int tc = (lane & 3) * 2;
#pragma unroll
    for (int i = 0; i < 4; i++) {
        const int r0 = bm + wm * 64 + i * 16 + tg;
#pragma unroll
        for (int j = 0; j < 8; j++) {
            const int col = bn + wn * 64 + j * 8 + tc;
            float v0 = acc[i][j][0], v1 = acc[i][j][1];
            float v2 = acc[i][j][2], v3 = acc[i][j][3];
            if (BIAS) {
                const float b0 = bias[col], b1 = bias[col + 1];
                v0 += b0; v1 += b1; v2 += b0; v3 += b1;
            }
            if (LEAKY) {
                v0 = v0 > 0.f ? v0 : 0.01f * v0;
                v1 = v1 > 0.f ? v1 : 0.01f * v1;
                v2 = v2 > 0.f ? v2 : 0.01f * v2;
                v3 = v3 > 0.f ? v3 : 0.01f * v3;
            }
            if (SPLIT) {
                uint32_t h01, l01, h23, l23;
                split2(v0, v1, h01, l01);
                split2(v2, v3, h23, l23);
                *(uint32_t*)&Chi[(size_t)r0 * N + col]       = h01;
                *(uint32_t*)&Clo[(size_t)r0 * N + col]       = l01;
                *(uint32_t*)&Chi[(size_t)(r0 + 8) * N + col] = h23;
                *(uint32_t*)&Clo[(size_t)(r0 + 8) * N + col] = l23;
            } else {
                *(float2*)&C[(size_t)r0 * N + col]       = make_float2(v0, v1);
                *(float2*)&C[(size_t)(r0 + 8) * N + col] = make_float2(v2, v3);
            }
        }
    }
}

template <int BIAS, int LEAKY, int SPLIT>
__global__ void __launch_bounds__(256, 1)
gemm_hmma(const __nv_bfloat16* __restrict__ Ah, const __nv_bfloat16* __restrict__ Al,
          const __nv_bfloat16* __restrict__ Bh, const __nv_bfloat16* __restrict__ Bl,
          const float* __restrict__ bias, float* __restrict__ C,
          __nv_bfloat16* __restrict__ Chi, __nv_bfloat16* __restrict__ Clo,
          int N, int K)
{
    extern __shared__ __align__(16) char smem[];
    gemm_body<BIAS, LEAKY, SPLIT>(Ah, Al, Bh, Bl, bias, C, Chi, Clo,
                                  N, K, blockIdx.y * 128, blockIdx.x * 256, smem);
}

__global__ void __launch_bounds__(256, 1)
gemm_dual(const __nv_bfloat16* A0h, const __nv_bfloat16* A0l,
          const __nv_bfloat16* W0h, const __nv_bfloat16* W0l,
          __nv_bfloat16* C0h, __nv_bfloat16* C0l, int N0, int nb0,
          const __nv_bfloat16* A1h, const __nv_bfloat16* A1l,
          const __nv_bfloat16* W1h, const __nv_bfloat16* W1l,
          __nv_bfloat16* C1h, __nv_bfloat16* C1l, int N1, int K)
{
    extern __shared__ __align__(16) char smem[];
    if ((int)blockIdx.x < nb0)
        gemm_body<0, 0, 1>(A0h, A0l, W0h, W0l, nullptr, nullptr, C0h, C0l,
                           N0, K, blockIdx.y * 128, blockIdx.x * 256, smem);
    else
        gemm_body<0, 0, 1>(A1h, A1l, W1h, W1l, nullptr, nullptr, C1h, C1l,
                           N1, K, blockIdx.y * 128, (blockIdx.x - nb0) * 256, smem);
}

// ---------------------------------------------------------------------------
// HMMA flash attention, split-bf16, cp.async 2-stage K/V pipeline (R8).
// ---------------------------------------------------------------------------
#define AROWB 144
#define KV_STAGE 36864
#define ATT_SMEM (2 * 18432 + 2 * KV_STAGE)    // 110592

__global__ void __launch_bounds__(256, 2)
attn_hmma(const __nv_bfloat16* __restrict__ Qh, const __nv_bfloat16* __restrict__ Ql,
          int qs,
          const __nv_bfloat16* __restrict__ Kh, const __nv_bfloat16* __restrict__ Kl,
          const __nv_bfloat16* __restrict__ Vh, const __nv_bfloat16* __restrict__ Vl,
          int kvs,
          const int* __restrict__ vlp, int per_row,
          __nv_bfloat16* __restrict__ Oh, __nv_bfloat16* __restrict__ Ol)
{
    PDL_TRIGGER();
    extern __shared__ __align__(16) char sm[];
    char* cQh = sm;
    char* cQl = sm + 18432;
    const uint32_t uQh = smem_u32(cQh), uQl = smem_u32(cQl);
    const uint32_t uKV = smem_u32(sm + 36864);
    __shared__ int sred[8];

    const int tid = threadIdx.x;
    const int w = tid >> 5, lane = tid & 31;
    const int g = lane >> 2, c = lane & 3;
    const int b = blockIdx.x >> 3, h = blockIdx.x & 7;
    const int q0 = blockIdx.y * 128;

    int kmax;
    if (per_row) {
        int v = (tid < 128) ? vlp[b * T_ + q0 + tid] : 0;
#pragma unroll
        for (int off = 16; off; off >>= 1)
            v = max(v, __shfl_xor_sync(0xffffffffu, v, off));
        if (lane == 0) sred[w] = v;
        __syncthreads();
        kmax = sred[0];
#pragma unroll
        for (int i = 1; i < 8; i++) kmax = max(kmax, sred[i]);
    } else {
        kmax = vlp[b];
    }
    const int nkt = (kmax + 63) >> 6;

    int vl0, vl1;
    if (per_row) {
        vl0 = vlp[b * T_ + q0 + w * 16 + g];
        vl1 = vlp[b * T_ + q0 + w * 16 + g + 8];
    } else {
        vl0 = vl1 = kmax;
    }

    PDL_WAIT();

    const __nv_bfloat16* qhp = Qh + (size_t)(b * T_ + q0) * qs + h * 64;
    const __nv_bfloat16* qlp = Ql + (size_t)(b * T_ + q0) * qs + h * 64;
    for (int i = tid; i < 1024; i += 256) {
        const int r = i >> 3, ch = i & 7;
        const size_t go = (size_t)r * qs + ch * 8;
        const uint32_t so = r * AROWB + ch * 16;
        *(uint4*)(cQh + so) = *(const uint4*)(qhp + go);
        *(uint4*)(cQl + so) = *(const uint4*)(qlp + go);
    }

    auto load_kv = [&](int kt, int stg) {
        const size_t kb = (size_t)(b * T_ + kt * 64) * kvs + h * 64;
        const uint32_t sb = uKV + stg * KV_STAGE;
        for (int i = tid; i < 512; i += 256) {
            const int r = i >> 3, ch = i & 7;
            const size_t go = kb + (size_t)r * kvs + ch * 8;
            const uint32_t so = r * AROWB + ch * 16;
            CP_ASYNC16(sb + so,         Kh + go);
            CP_ASYNC16(sb + 9216 + so,  Kl + go);
            CP_ASYNC16(sb + 18432 + so, Vh + go);
            CP_ASYNC16(sb + 27648 + so, Vl + go);
        }
        CP_COMMIT();
    };
    load_kv(0, 0);

    float m0 = -1e30f, m1 = -1e30f, l0 = 0.f, l1 = 0.f;
    float o[8][4];
#pragma unroll
    for (int j = 0; j < 8; j++)
#pragma unroll
        for (int e = 0; e < 4; e++) o[j][e] = 0.f;

    const uint32_t qaddr = (w * 16 + (lane & 15)) * AROWB + (lane >> 4) * 16;
    const int bRow = (lane & 7) + ((lane >> 4) << 3);
    const int bK8  = ((lane >> 3) & 1) * 16;
    const int vRow = (lane & 7) + ((lane >> 3) & 1) * 8;
    const int vColB = (lane >> 4) * 16;

    for (int kt = 0; kt < nkt; kt++) {
        __syncthreads();
        if (kt + 1 < nkt) {
            load_kv(kt + 1, (kt + 1) & 1);
            CP_WAIT(1);
        } else {
            CP_WAIT(0);
        }
        __syncthreads();

        const uint32_t sK  = uKV + (kt & 1) * KV_STAGE;
        const uint32_t uKh = sK, uKl = sK + 9216;
        const uint32_t uVh = sK + 18432, uVl = sK + 27648;

        float s[8][4];
#pragma unroll
        for (int j = 0; j < 8; j++)
#pragma unroll
            for (int e = 0; e < 4; e++) s[j][e] = 0.f;

#pragma unroll
        for (int kk = 0; kk < 4; kk++) {
            uint32_t ah0, ah1, ah2, ah3, al0, al1, al2, al3;
            LDMATRIX_X4(ah0, ah1, ah2, ah3, uQh + qaddr + kk * 32);
            LDMATRIX_X4(al0, al1, al2, al3, uQl + qaddr + kk * 32);
#pragma unroll
            for (int j2 = 0; j2 < 4; j2++) {
                uint32_t r0, r1, r2, r3;
                LDMATRIX_X4(r0, r1, r2, r3,
                            uKh + (j2 * 16 + bRow) * AROWB + kk * 32 + bK8);
                MMA_BF16(s[2*j2][0], s[2*j2][1], s[2*j2][2], s[2*j2][3],
                         ah0, ah1, ah2, ah3, r0, r1);
                MMA_BF16(s[2*j2+1][0], s[2*j2+1][1], s[2*j2+1][2], s[2*j2+1][3],
                         ah0, ah1, ah2, ah3, r2, r3);
                MMA_BF16(s[2*j2][0], s[2*j2][1], s[2*j2][2], s[2*j2][3],
                         al0, al1, al2, al3, r0, r1);
                MMA_BF16(s[2*j2+1][0], s[2*j2+1][1], s[2*j2+1][2], s[2*j2+1][3],
                         al0, al1, al2, al3, r2, r3);
            }
#pragma unroll
            for (int j2 = 0; j2 < 4; j2++) {
                uint32_t r0, r1, r2, r3;
                LDMATRIX_X4(r0, r1, r2, r3,
                            uKl + (j2 * 16 + bRow) * AROWB + kk * 32 + bK8);
                MMA_BF16(s[2*j2][0], s[2*j2][1], s[2*j2][2], s[2*j2][3],
                         ah0, ah1, ah2, ah3, r0, r1);
                MMA_BF16(s[2*j2+1][0], s[2*j2+1][1], s[2*j2+1][2], s[2*j2+1][3],
                         ah0, ah1, ah2, ah3, r2, r3);
            }
        }

        const int kof = kt * 64 + c * 2;
        float mx0 = -1e30f, mx1 = -1e30f;
#pragma unroll
        for (int j = 0; j < 8; j++) {
            const int ki = kof + j * 8;
            s[j][0] = (ki     < vl0) ? s[j][0] * 0.125f : -1e10f;
            s[j][1] = (ki + 1 < vl0) ? s[j][1] * 0.125f : -1e10f;
            s[j][2] = (ki     < vl1) ? s[j][2] * 0.125f : -1e10f;
            s[j][3] = (ki + 1 < vl1) ? s[j][3] * 0.125f : -1e10f;
            mx0 = fmaxf(mx0, fmaxf(s[j][0], s[j][1]));
            mx1 = fmaxf(mx1, fmaxf(s[j][2], s[j][3]));
        }
        mx0 = fmaxf(mx0, __shfl_xor_sync(0xffffffffu, mx0, 1));
        mx0 = fmaxf(mx0, __shfl_xor_sync(0xffffffffu, mx0, 2));
        mx1 = fmaxf(mx1, __shfl_xor_sync(0xffffffffu, mx1, 1));
        mx1 = fmaxf(mx1, __shfl_xor_sync(0xffffffffu, mx1, 2));

        const float mn0 = fmaxf(m0, mx0), mn1 = fmaxf(m1, mx1);
        const float al_0 = __expf(m0 - mn0), al_1 = __expf(m1 - mn1);
        m0 = mn0; m1 = mn1;

        float rs0 = 0.f, rs1 = 0.f;
#pragma unroll
        for (int j = 0; j < 8; j++) {
            s[j][0] = __expf(s[j][0] - mn0);
            s[j][1] = __expf(s[j][1] - mn0);
            s[j][2] = __expf(s[j][2] - mn1);
            s[j][3] = __expf(s[j][3] - mn1);
            rs0 += s[j][0] + s[j][1];
            rs1 += s[j][2] + s[j][3];
        }
        rs0 += __shfl_xor_sync(0xffffffffu, rs0, 1);
        rs0 += __shfl_xor_sync(0xffffffffu, rs0, 2);
        rs1 += __shfl_xor_sync(0xffffffffu, rs1, 1);
        rs1 += __shfl_xor_sync(0xffffffffu, rs1, 2);
        l0 = l0 * al_0 + rs0;
        l1 = l1 * al_1 + rs1;

#pragma unroll
        for (int j = 0; j < 8; j++) {
            o[j][0] *= al_0; o[j][1] *= al_0;
            o[j][2] *= al_1; o[j][3] *= al_1;
        }

#pragma unroll
        for (int t = 0; t < 4; t++) {
            uint32_t ph[4], pl[4];
            split2(s[2*t][0],   s[2*t][1],   ph[0], pl[0]);
            split2(s[2*t][2],   s[2*t][3],   ph[1], pl[1]);
            split2(s[2*t+1][0], s[2*t+1][1], ph[2], pl[2]);
            split2(s[2*t+1][2], s[2*t+1][3], ph[3], pl[3]);
#pragma unroll
            for (int j2 = 0; j2 < 4; j2++) {
                uint32_t r0, r1, r2, r3;
                LDMATRIX_X4_T(r0, r1, r2, r3,
                              uVh + (t * 16 + vRow) * AROWB + j2 * 32 + vColB);
                MMA_BF16(o[2*j2][0], o[2*j2][1], o[2*j2][2], o[2*j2][3],
                         ph[0], ph[1], ph[2], ph[3], r0, r1);
                MMA_BF16(o[2*j2+1][0], o[2*j2+1][1], o[2*j2+1][2], o[2*j2+1][3],
                         ph[0], ph[1], ph[2], ph[3], r2, r3);
                MMA_BF16(o[2*j2][0], o[2*j2][1], o[2*j2][2], o[2*j2][3],
                         pl[0], pl[1], pl[2], pl[3], r0, r1);
                MMA_BF16(o[2*j2+1][0], o[2*j2+1][1], o[2*j2+1][2], o[2*j2+1][3],
                         pl[0], pl[1], pl[2], pl[3], r2, r3);
            }
#pragma unroll
            for (int j2 = 0; j2 < 4; j2++) {
                uint32_t r0, r1, r2, r3;
                LDMATRIX_X4_T(r0, r1, r2, r3,
                              uVl + (t * 16 + vRow) * AROWB + j2 * 32 + vColB);
                MMA_BF16(o[2*j2][0], o[2*j2][1], o[2*j2][2], o[2*j2][3],
                         ph[0], ph[1], ph[2], ph[3], r0, r1);
                MMA_BF16(o[2*j2+1][0], o[2*j2+1][1], o[2*j2+1][2], o[2*j2+1][3],
                         ph[0], ph[1], ph[2], ph[3], r2, r3);
            }
        }
    }

    const float il0 = 1.0f / l0, il1 = 1.0f / l1;
    const int r0g = b * T_ + q0 + w * 16 + g;
    const int r1g = r0g + 8;
#pragma unroll
    for (int j = 0; j < 8; j++) {
        const int col = h * 64 + j * 8 + c * 2;
        uint32_t hi, lo;
        split2(o[j][0] * il0, o[j][1] * il0, hi, lo);
        *(uint32_t*)&Oh[(size_t)r0g * D_ + col] = hi;
        *(uint32_t*)&Ol[(size_t)r0g * D_ + col] = lo;
        split2(o[j][2] * il1, o[j][3] * il1, hi, lo);
        *(uint32_t*)&Oh[(size_t)r1g * D_ + col] = hi;
        *(uint32_t*)&Ol[(size_t)r1g * D_ + col] = lo;
    }
}

// ---------------------------------------------------------------------------
// out = LayerNorm(A + Bt) * g + be ; SPLIT=1 also emits bf16 hi/lo
// ---------------------------------------------------------------------------
template <int SPLIT>
__global__ void __launch_bounds__(128)
addnorm_kernel(const float* __restrict__ A, const float* __restrict__ Bt,
               const float* __restrict__ g, const float* __restrict__ be,
               float* __restrict__ out,
               __nv_bfloat16* __restrict__ ohi, __nv_bfloat16* __restrict__ olo)
{
    PDL_TRIGGER();
    PDL_WAIT();
    const int row = blockIdx.x;
    const int tid = threadIdx.x;
    const size_t base = (size_t)row * D_;

    float4 a = *(const float4*)&A[base + tid * 4];
    float4 b = *(const float4*)&Bt[base + tid * 4];
    float4 x = make_float4(a.x + b.x, a.y + b.y, a.z + b.z, a.w + b.w);

    float s  = x.x + x.y + x.z + x.w;
    float sq = x.x * x.x + x.y * x.y + x.z * x.z + x.w * x.w;
#pragma unroll
    for (int off = 16; off; off >>= 1) {
        s  += __shfl_xor_sync(0xffffffffu, s,  off);
        sq += __shfl_xor_sync(0xffffffffu, sq, off);
    }
    __shared__ float ss[4], ssq[4];
    if ((tid & 31) == 0) { ss[tid >> 5] = s; ssq[tid >> 5] = sq; }
    __syncthreads();
    s  = ss[0] + ss[1] + ss[2] + ss[3];
    sq = ssq[0] + ssq[1] + ssq[2] + ssq[3];

    float mu  = s * (1.0f / D_);
    float var = sq * (1.0f / D_) - mu * mu;
    float inv = rsqrtf(var + 1e-5f);

    float4 gg = *(const float4*)&g[tid * 4];
    float4 bb = *(const float4*)&be[tid * 4];
    float4 oo = make_float4((x.x - mu) * inv * gg.x + bb.x,
                            (x.y - mu) * inv * gg.y + bb.y,
                            (x.z - mu) * inv * gg.z + bb.z,
                            (x.w - mu) * inv * gg.w + bb.w);
    *(float4*)&out[base + tid * 4] = oo;
    if (SPLIT) {
        uint32_t h0, l0, h1, l1;
        split2(oo.x, oo.y, h0, l0);
        split2(oo.z, oo.w, h1, l1);
        uint32_t* hp = (uint32_t*)&ohi[base + tid * 4];
        uint32_t* lp = (uint32_t*)&olo[base + tid * 4];
        hp[0] = h0; hp[1] = h1;
        lp[0] = l0; lp[1] = l1;
    }
}

// ---------------------------------------------------------------------------
// PDL launch helper
// ---------------------------------------------------------------------------
template <typename... ExpT, typename... ActT>
static void launch_pdl(void (*kern)(ExpT...), dim3 gr, dim3 bl, size_t shm,
                       ActT... args)
{
    cudaLaunchConfig_t cfg = {};
    cfg.gridDim = gr;
    cfg.blockDim = bl;
    cfg.dynamicSmemBytes = shm;
    cfg.stream = 0;
    cudaLaunchAttribute at[1];
    at[0].id = cudaLaunchAttributeProgrammaticStreamSerialization;
    at[0].val.programmaticStreamSerializationAllowed = 1;
    cfg.attrs = at;
    cfg.numAttrs = 1;
    cudaLaunchKernelEx(&cfg, kern, args...);
}

// ---------------------------------------------------------------------------
// Launch
// ---------------------------------------------------------------------------
extern "C" void kernel_launch(void* const* d_in, const int* in_sizes, int n_in,
                              void* d_out, int out_size)
{
    const float* X    = (const float*)d_in[0];
    const float* ENC  = (const float*)d_in[1];
    const int*   DVL  = (const int*)d_in[2];
    const int*   EVL  = (const int*)d_in[3];
    const float* Wmat[8] = {
        (const float*)d_in[4],  (const float*)d_in[5],
        (const float*)d_in[6],  (const float*)d_in[7],
        (const float*)d_in[8],  (const float*)d_in[9],
        (const float*)d_in[10], (const float*)d_in[11]};
    const float* W1   = (const float*)d_in[12];
    const float* b1   = (const float*)d_in[13];
    const float* W2   = (const float*)d_in[14];
    const float* b2   = (const float*)d_in[15];
    const float* G1   = (const float*)d_in[16];
    const float* BE1  = (const float*)d_in[17];
    const float* G2   = (const float*)d_in[18];
    const float* BE2  = (const float*)d_in[19];
    const float* G3   = (const float*)d_in[20];
    const float* BE3  = (const float*)d_in[21];
    float* out = (float*)d_out;

    float *tmp, *Y, *Z;
    __nv_bfloat16 *h1, *l1, *h2, *l2, *qkvh, *qkvl, *kvh, *kvl;
    __nv_bfloat16 *q2h, *q2l, *ath, *atl, *Fh, *Fl, *Wh, *Wl;
    cudaGetSymbolAddress((void**)&tmp,  g_tmp);
    cudaGetSymbolAddress((void**)&Y,    g_Y);
    cudaGetSymbolAddress((void**)&Z,    g_Z);
    cudaGetSymbolAddress((void**)&h1,   g_h1);
    cudaGetSymbolAddress((void**)&l1,   g_l1);
    cudaGetSymbolAddress((void**)&h2,   g_h2);
    cudaGetSymbolAddress((void**)&l2,   g_l2);
    cudaGetSymbolAddress((void**)&qkvh, g_qkvh);
    cudaGetSymbolAddress((void**)&qkvl, g_qkvl);
    cudaGetSymbolAddress((void**)&kvh,  g_kvh);
    cudaGetSymbolAddress((void**)&kvl,  g_kvl);
    cudaGetSymbolAddress((void**)&q2h,  g_q2h);
    cudaGetSymbolAddress((void**)&q2l,  g_q2l);
    cudaGetSymbolAddress((void**)&ath,  g_ath);
    cudaGetSymbolAddress((void**)&atl,  g_atl);
    cudaGetSymbolAddress((void**)&Fh,   g_Fh);
    cudaGetSymbolAddress((void**)&Fl,   g_Fl);
    cudaGetSymbolAddress((void**)&Wh,   g_Wh);
    cudaGetSymbolAddress((void**)&Wl,   g_Wl);

    cudaFuncSetAttribute(attn_hmma,
                         cudaFuncAttributeMaxDynamicSharedMemorySize, ATT_SMEM);
    cudaFuncSetAttribute(gemm_hmma<0, 0, 1>,
                         cudaFuncAttributeMaxDynamicSharedMemorySize, GEMM_SMEM);
    cudaFuncSetAttribute(gemm_hmma<0, 0, 0>,
                         cudaFuncAttributeMaxDynamicSharedMemorySize, GEMM_SMEM);
    cudaFuncSetAttribute(gemm_hmma<1, 1, 1>,
                         cudaFuncAttributeMaxDynamicSharedMemorySize, GEMM_SMEM);
    cudaFuncSetAttribute(gemm_hmma<1, 0, 0>,
                         cudaFuncAttributeMaxDynamicSharedMemorySize, GEMM_SMEM);
    cudaFuncSetAttribute(gemm_dual,
                         cudaFuncAttributeMaxDynamicSharedMemorySize, GEMM_SMEM);

    size_t WO[10];
    for (int i = 0; i < 8; i++) WO[i] = (size_t)i * D_ * D_;
    WO[8] = 8ull * D_ * D_;
    WO[9] = WO[8] + (size_t)F_ * D_;

    const int nDD = D_ * D_ / 4;       // 65536
    const int nMD = M_ * D_ / 4;       // 2097152
    const int nFD = F_ * D_ / 4;       // 262144

    SplitSegs segs;
    int total4 = 0;
    for (int i = 0; i < 8; i++) {
        segs.src[i] = Wmat[i];
        segs.hi[i] = Wh + WO[i]; segs.lo[i] = Wl + WO[i];
        segs.n4[i] = nDD; total4 += nDD;
    }
    segs.src[8] = W1; segs.hi[8] = Wh + WO[8]; segs.lo[8] = Wl + WO[8];
    segs.n4[8] = nFD; total4 += nFD;
    segs.src[9] = W2; segs.hi[9] = Wh + WO[9]; segs.lo[9] = Wl + WO[9];
    segs.n4[9] = nFD; total4 += nFD;
    segs.src[10] = X;   segs.hi[10] = h1; segs.lo[10] = l1;
    segs.n4[10] = nMD; total4 += nMD;
    segs.src[11] = ENC; segs.hi[11] = h2; segs.lo[11] = l2;
    segs.n4[11] = nMD; total4 += nMD;
    launch_pdl(msplit_kernel, dim3((total4 + 255) / 256), dim3(256), 0, segs);

    dim3 gQKV(1536 / 256, M_ / 128);   // (6, 128)
    dim3 gDUO(6,          M_ / 128);   // q2(2) + kv(4)
    dim3 gP  (D_ / 256,   M_ / 128);   // (2, 128)
    dim3 gF1 (F_ / 256,   M_ / 128);   // (8, 128)
    dim3 gA  (B_ * H_,    T_ / 128);   // (256, 4)
    dim3 gAN (M_);

    // ---- self-attention ----
    launch_pdl(gemm_hmma<0,0,1>, gQKV, dim3(256), GEMM_SMEM,
               (const __nv_bfloat16*)h1, (const __nv_bfloat16*)l1,
               (const __nv_bfloat16*)(Wh + WO[0]), (const __nv_bfloat16*)(Wl + WO[0]),
               (const float*)nullptr, (float*)nullptr, qkvh, qkvl, 1536, D_);
    launch_pdl(attn_hmma, gA, dim3(256), (size_t)ATT_SMEM,
               (const __nv_bfloat16*)qkvh, (const __nv_bfloat16*)qkvl, 1536,
               (const __nv_bfloat16*)(qkvh + 512), (const __nv_bfloat16*)(qkvl + 512),
               (const __nv_bfloat16*)(qkvh + 1024), (const __nv_bfloat16*)(qkvl + 1024), 1536,
               DVL, 1, ath, atl);
    launch_pdl(gemm_hmma<0,0,0>, gP, dim3(256), GEMM_SMEM,
               (const __nv_bfloat16*)ath, (const __nv_bfloat16*)atl,
               (const __nv_bfloat16*)(Wh + WO[3]), (const __nv_bfloat16*)(Wl + WO[3]),
               (const float*)nullptr, tmp, (__nv_bfloat16*)nullptr, (__nv_bfloat16*)nullptr,
               D_, D_);
    launch_pdl(addnorm_kernel<1>, gAN, dim3(128), 0,
               X, (const float*)tmp, G1, BE1, Y, h1, l1);

    // ---- cross-attention (Q2 + KV in one launch) ----
    launch_pdl(gemm_dual, gDUO, dim3(256), GEMM_SMEM,
               (const __nv_bfloat16*)h1, (const __nv_bfloat16*)l1,
               (const __nv_bfloat16*)(Wh + WO[4]), (const __nv_bfloat16*)(Wl + WO[4]),
               q2h, q2l, 512, 2,
               (const __nv_bfloat16*)h2, (const __nv_bfloat16*)l2,
               (const __nv_bfloat16*)(Wh + WO[5]), (const __nv_bfloat16*)(Wl + WO[5]),
               kvh, kvl, 1024, D_);
    launch_pdl(attn_hmma, gA, dim3(256), (size_t)ATT_SMEM,
               (const __nv_bfloat16*)q2h, (const __nv_bfloat16*)q2l, D_,
               (const __nv_bfloat16*)kvh, (const __nv_bfloat16*)kvl,
               (const __nv_bfloat16*)(kvh + 512), (const __nv_bfloat16*)(kvl + 512), 1024,
               EVL, 0, ath, atl);
    launch_pdl(gemm_hmma<0,0,0>, gP, dim3(256), GEMM_SMEM,
               (const __nv_bfloat16*)ath, (const __nv_bfloat16*)atl,
               (const __nv_bfloat16*)(Wh + WO[7]), (const __nv_bfloat16*)(Wl + WO[7]),
               (const float*)nullptr, tmp, (__nv_bfloat16*)nullptr, (__nv_bfloat16*)nullptr,
               D_, D_);
    launch_pdl(addnorm_kernel<1>, gAN, dim3(128), 0,
               (const float*)Y, (const float*)tmp, G2, BE2, Z, h2, l2);

    // ---- FFN ----
    launch_pdl(gemm_hmma<1,1,1>, gF1, dim3(256), GEMM_SMEM,
               (const __nv_bfloat16*)h2, (const __nv_bfloat16*)l2,
               (const __nv_bfloat16*)(Wh + WO[8]), (const __nv_bfloat16*)(Wl + WO[8]),
               b1, (float*)nullptr, Fh, Fl, F_, D_);
    launch_pdl(gemm_hmma<1,0,0>, gP, dim3(256), GEMM_SMEM,
               (const __nv_bfloat16*)Fh, (const __nv_bfloat16*)Fl,
               (const __nv_bfloat16*)(Wh + WO[9]), (const __nv_bfloat16*)(Wl + WO[9]),
               b2, tmp, (__nv_bfloat16*)nullptr, (__nv_bfloat16*)nullptr, D_, F_);
    launch_pdl(addnorm_kernel<0>, gAN, dim3(128), 0,
               (const float*)Z, (const float*)tmp, G3, BE3, out,
               (__nv_bfloat16*)nullptr, (__nv_bfloat16*)nullptr);
}

// round 14
// speedup vs baseline: 2.3826x; 2.3826x over previous
#include <cuda_runtime.h>
#include <cuda_fp16.h>
#include <math.h>
#include <stdint.h>

// Problem constants
#define B_ 32
#define T_ 512
#define D_ 512
#define H_ 8
#define M_ (B_ * T_)   // 16384 rows
#define F_ 2048

// ---------------------------------------------------------------------------
// Scratch (device globals; no allocation allowed)
// ---------------------------------------------------------------------------
__device__ float g_tmp[(size_t)M_ * D_];
__device__ float g_Y  [(size_t)M_ * D_];
__device__ float g_Z  [(size_t)M_ * D_];

__device__ __half g_x1 [(size_t)M_ * D_];     // X / Y (fp16)
__device__ __half g_x2 [(size_t)M_ * D_];     // ENC / Z (fp16)
__device__ __half g_qkv[(size_t)M_ * 1536];   // self QKV fused
__device__ __half g_kv [(size_t)M_ * 1024];   // cross KV fused
__device__ __half g_q2 [(size_t)M_ * D_];     // cross Q
__device__ __half g_at [(size_t)M_ * D_];     // attention output
__device__ __half g_F  [(size_t)M_ * F_];     // FFN intermediate
__device__ __half g_W  [4194304];             // all weights fp16

// ---------------------------------------------------------------------------
// helpers
// ---------------------------------------------------------------------------
__device__ __forceinline__ uint32_t smem_u32(const void* p) {
    uint32_t a;
    asm("{ .reg .u64 t; cvta.to.shared.u64 t, %1; cvt.u32.u64 %0, t; }"
        : "=r"(a) : "l"(p));
    return a;
}

#define PDL_TRIGGER() asm volatile("griddepcontrol.launch_dependents;" ::: "memory")
#define PDL_WAIT()    asm volatile("griddepcontrol.wait;" ::: "memory")

#define CP_ASYNC16(dst, src) \
    asm volatile("cp.async.cg.shared.global [%0], [%1], 16;" :: \
                 "r"(dst), "l"(src) : "memory")
#define CP_COMMIT() asm volatile("cp.async.commit_group;" ::: "memory")
#define CP_WAIT(n)  asm volatile("cp.async.wait_group %0;" :: "n"(n) : "memory")

#define LDMATRIX_X4(r0, r1, r2, r3, addr) \
    asm volatile("ldmatrix.sync.aligned.m8n8.x4.shared.b16 {%0,%1,%2,%3}, [%4];" \
                 : "=r"(r0), "=r"(r1), "=r"(r2), "=r"(r3) : "r"(addr))

#define LDMATRIX_X4_T(r0, r1, r2, r3, addr) \
    asm volatile("ldmatrix.sync.aligned.m8n8.x4.trans.shared.b16 {%0,%1,%2,%3}, [%4];" \
                 : "=r"(r0), "=r"(r1), "=r"(r2), "=r"(r3) : "r"(addr))

#define MMA_F16(d0, d1, d2, d3, a0, a1, a2, a3, b0, b1) \
    asm volatile("mma.sync.aligned.m16n8k16.row.col.f32.f16.f16.f32 " \
                 "{%0,%1,%2,%3}, {%4,%5,%6,%7}, {%8,%9}, {%0,%1,%2,%3};" \
                 : "+f"(d0), "+f"(d1), "+f"(d2), "+f"(d3) \
                 : "r"(a0), "r"(a1), "r"(a2), "r"(a3), "r"(b0), "r"(b1))

__device__ __forceinline__ uint32_t packh2(float x, float y) {
    __half2 h = __floats2half2_rn(x, y);
    return *reinterpret_cast<uint32_t*>(&h);
}

// ---------------------------------------------------------------------------
// merged convert fp32 -> fp16: 12 segments in one launch
// ---------------------------------------------------------------------------
struct ConvSegs {
    const float* src[12];
    __half* dst[12];
    int n4[12];
};

__global__ void __launch_bounds__(256)
mconv_kernel(ConvSegs s)
{
    PDL_TRIGGER();
    int i = blockIdx.x * 256 + threadIdx.x;
#pragma unroll
    for (int k = 0; k < 12; k++) {
        if (i < s.n4[k]) {
            float4 v = ((const float4*)s.src[k])[i];
            uint32_t* dp = (uint32_t*)s.dst[k];
            dp[2 * i]     = packh2(v.x, v.y);
            dp[2 * i + 1] = packh2(v.z, v.w);
            return;
        }
        i -= s.n4[k];
    }
}

// ---------------------------------------------------------------------------
// fp16 HMMA GEMM: C[M,N] = A[M,K] @ W[N,K]^T (single pass, fp32 accum)
// 128x128 CTA tile, 256 threads, 8 warps (2 M x 4 N), warp tile 64x32.
// XOR-swizzled 64B-row SMEM, 4-stage cp.async pipeline (prefetch dist 3).
// ---------------------------------------------------------------------------
#define TILE_H 8192                  // 128 rows x 64 B
#define STAGE_B (2 * TILE_H)         // A + B = 16384
#define GEMM_SMEM (4 * STAGE_B)      // 65536

template <int BIAS, int LEAKY, int CONV>
__device__ __forceinline__ void gemm_body(
    const __half* __restrict__ A, const __half* __restrict__ W,
    const float* __restrict__ bias, float* __restrict__ C,
    __half* __restrict__ Ch,
    int N, int K, int bm, int bn, char* smem)
{
    PDL_TRIGGER();
    const uint32_t sbase = smem_u32(smem);

    const int tid = threadIdx.x;
    const int wid = tid >> 5, lane = tid & 31;
    const int wm = wid & 1, wn = wid >> 1;     // 2 M x 4 N warp grid

    const int ldr0 = tid >> 2;            // row 0..63
    const int ldc4 = tid & 3;             // 16B-chunk 0..3
    const int ldce = ldc4 * 8;            // element col

    const __half* gA = A + (size_t)(bm + ldr0) * K + ldce;
    const __half* gW = W + (size_t)(bn + ldr0) * K + ldce;
    const size_t rstep = (size_t)64 * K;

    uint32_t sro[2];
#pragma unroll
    for (int h = 0; h < 2; h++) {
        const int r = ldr0 + h * 64;
        sro[h] = (uint32_t)(r * 64 + ((ldc4 ^ ((r >> 1) & 3)) << 4));
    }

    const int aRowB = wm * 64 + (lane & 15);
    const int aKc0  = (lane >> 4);
    const int aSw   = (aRowB >> 1) & 3;
    const int bRowB = wn * 32 + (lane & 7) + ((lane >> 4) << 3);
    const int bKc0  = (lane >> 3) & 1;
    const int bSw   = (bRowB >> 1) & 3;

    float acc[4][4][4];
#pragma unroll
    for (int i = 0; i < 4; i++)
#pragma unroll
        for (int j = 0; j < 4; j++)
#pragma unroll
            for (int r = 0; r < 4; r++) acc[i][j][r] = 0.f;

    const int NC = K >> 5;

    auto load_chunk = [&](int c) {
        const uint32_t st = sbase + (c & 3) * STAGE_B;
        const int koff = c << 5;
#pragma unroll
        for (int h = 0; h < 2; h++) {
            CP_ASYNC16(st + sro[h],          gA + (size_t)h * rstep + koff);
            CP_ASYNC16(st + TILE_H + sro[h], gW + (size_t)h * rstep + koff);
        }
        CP_COMMIT();
    };

    PDL_WAIT();
    load_chunk(0);
    load_chunk(1);
    load_chunk(2);

    for (int c = 0; c < NC; c++) {
        // groups pending for chunks c..min(c+2, NC-1); require chunk c done
        const int pend = NC - 1 - c;
        if (pend >= 2)      { CP_WAIT(2); }
        else if (pend == 1) { CP_WAIT(1); }
        else                { CP_WAIT(0); }
        __syncthreads();
        if (c + 3 < NC) load_chunk(c + 3);

        const uint32_t st = sbase + (c & 3) * STAGE_B;
        const uint32_t aB = st, bB = st + TILE_H;

#pragma unroll
        for (int ks = 0; ks < 2; ks++) {
            const uint32_t aoff = (uint32_t)(aRowB * 64 +
                                  (((ks * 2 + aKc0) ^ aSw) << 4));
            const uint32_t boff = (uint32_t)(bRowB * 64 +
                                  (((ks * 2 + bKc0) ^ bSw) << 4));

            uint32_t b[4][2];
#pragma unroll
            for (int j2 = 0; j2 < 2; j2++) {
                uint32_t r0, r1, r2, r3;
                LDMATRIX_X4(r0, r1, r2, r3, bB + boff + j2 * 1024);
                b[j2 * 2 + 0][0] = r0; b[j2 * 2 + 0][1] = r1;
                b[j2 * 2 + 1][0] = r2; b[j2 * 2 + 1][1] = r3;
            }
            uint32_t a[4][4];
#pragma unroll
            for (int i = 0; i < 4; i++)
                LDMATRIX_X4(a[i][0], a[i][1], a[i][2], a[i][3],
                            aB + aoff + i * 1024);
#pragma unroll
            for (int i = 0; i < 4; i++)
#pragma unroll
                for (int j = 0; j < 4; j++)
                    MMA_F16(acc[i][j][0], acc[i][j][1], acc[i][j][2], acc[i][j][3],
                            a[i][0], a[i][1], a[i][2], a[i][3], b[j][0], b[j][1]);
        }
    }

    const int tg = lane >> 2;
    const int tc = (lane & 3) * 2;
#pragma unroll
    for (int i = 0; i < 4; i++) {
        const int r0 = bm + wm * 64 + i * 16 + tg;
#pragma unroll
        for (int j = 0; j < 4; j++) {
            const int col = bn + wn * 32 + j * 8 + tc;
            float v0 = acc[i][j][0], v1 = acc[i][j][1];
            float v2 = acc[i][j][2], v3 = acc[i][j][3];
            if (BIAS) {
                const float b0 = bias[col], b1 = bias[col + 1];
                v0 += b0; v1 += b1; v2 += b0; v3 += b1;
            }
            if (LEAKY) {
                v0 = v0 > 0.f ? v0 : 0.01f * v0;
                v1 = v1 > 0.f ? v1 : 0.01f * v1;
                v2 = v2 > 0.f ? v2 : 0.01f * v2;
                v3 = v3 > 0.f ? v3 : 0.01f * v3;
            }
            if (CONV) {
                *(uint32_t*)&Ch[(size_t)r0 * N + col]       = packh2(v0, v1);
                *(uint32_t*)&Ch[(size_t)(r0 + 8) * N + col] = packh2(v2, v3);
            } else {
                *(float2*)&C[(size_t)r0 * N + col]       = make_float2(v0, v1);
                *(float2*)&C[(size_t)(r0 + 8) * N + col] = make_float2(v2, v3);
            }
        }
    }
}

template <int BIAS, int LEAKY, int CONV>
__global__ void __launch_bounds__(256, 2)
gemm_hmma(const __half* __restrict__ A, const __half* __restrict__ W,
          const float* __restrict__ bias, float* __restrict__ C,
          __half* __restrict__ Ch, int N, int K)
{
    extern __shared__ __align__(16) char smem[];
    gemm_body<BIAS, LEAKY, CONV>(A, W, bias, C, Ch,
                                 N, K, blockIdx.y * 128, blockIdx.x * 128, smem);
}

// Two independent fp16-out GEMM jobs in one launch (cross-attn Q2 + KV)
__global__ void __launch_bounds__(256, 2)
gemm_dual(const __half* A0, const __half* W0, __half* C0, int N0, int nb0,
          const __half* A1, const __half* W1, __half* C1, int N1, int K)
{
    extern __shared__ __align__(16) char smem[];
    if ((int)blockIdx.x < nb0)
        gemm_body<0, 0, 1>(A0, W0, nullptr, nullptr, C0,
                           N0, K, blockIdx.y * 128, blockIdx.x * 128, smem);
    else
        gemm_body<0, 0, 1>(A1, W1, nullptr, nullptr, C1,
                           N1, K, blockIdx.y * 128, (blockIdx.x - nb0) * 128, smem);
}

// ---------------------------------------------------------------------------
// fp16 HMMA flash attention (single pass), cp.async 2-stage K/V pipeline.
// Grid (B*H, T/128), 256 threads; warp w owns q-rows 16w..16w+15.
// ---------------------------------------------------------------------------
#define AROWB 144
#define KV_STAGE 18432                       // K (64x144) + V (64x144)
#define ATT_SMEM (18432 + 2 * KV_STAGE)      // Q + 2 stages = 55296

__global__ void __launch_bounds__(256, 2)
attn_hmma(const __half* __restrict__ Q, int qs,
          const __half* __restrict__ K, const __half* __restrict__ V, int kvs,
          const int* __restrict__ vlp, int per_row,
          __half* __restrict__ O)
{
    PDL_TRIGGER();
    extern __shared__ __align__(16) char sm[];
    char* cQ = sm;
    const uint32_t uQ  = smem_u32(cQ);
    const uint32_t uKV = smem_u32(sm + 18432);
    __shared__ int sred[8];

    const int tid = threadIdx.x;
    const int w = tid >> 5, lane = tid & 31;
    const int g = lane >> 2, c = lane & 3;
    const int b = blockIdx.x >> 3, h = blockIdx.x & 7;
    const int q0 = blockIdx.y * 128;

    int kmax;
    if (per_row) {
        int v = (tid < 128) ? vlp[b * T_ + q0 + tid] : 0;
#pragma unroll
        for (int off = 16; off; off >>= 1)
            v = max(v, __shfl_xor_sync(0xffffffffu, v, off));
        if (lane == 0) sred[w] = v;
        __syncthreads();
        kmax = sred[0];
#pragma unroll
        for (int i = 1; i < 8; i++) kmax = max(kmax, sred[i]);
    } else {
        kmax = vlp[b];
    }
    const int nkt = (kmax + 63) >> 6;

    int vl0, vl1;
    if (per_row) {
        vl0 = vlp[b * T_ + q0 + w * 16 + g];
        vl1 = vlp[b * T_ + q0 + w * 16 + g + 8];
    } else {
        vl0 = vl1 = kmax;
    }

    PDL_WAIT();

    // load Q tile (128 rows x 64 fp16)
    const __half* qp = Q + (size_t)(b * T_ + q0) * qs + h * 64;
    for (int i = tid; i < 1024; i += 256) {
        const int r = i >> 3, ch = i & 7;
        *(uint4*)(cQ + r * AROWB + ch * 16) =
            *(const uint4*)(qp + (size_t)r * qs + ch * 8);
    }

    auto load_kv = [&](int kt, int stg) {
        const size_t kb = (size_t)(b * T_ + kt * 64) * kvs + h * 64;
        const uint32_t sb = uKV + stg * KV_STAGE;
        for (int i = tid; i < 512; i += 256) {
            const int r = i >> 3, ch = i & 7;
            const size_t go = kb + (size_t)r * kvs + ch * 8;
            const uint32_t so = r * AROWB + ch * 16;
            CP_ASYNC16(sb + so,        K + go);
            CP_ASYNC16(sb + 9216 + so, V + go);
        }
        CP_COMMIT();
    };
    load_kv(0, 0);

    float m0 = -1e30f, m1 = -1e30f, l0 = 0.f, l1 = 0.f;
    float o[8][4];
#pragma unroll
    for (int j = 0; j < 8; j++)
#pragma unroll
        for (int e = 0; e < 4; e++) o[j][e] = 0.f;

    const uint32_t qaddr = (w * 16 + (lane & 15)) * AROWB + (lane >> 4) * 16;
    const int bRow = (lane & 7) + ((lane >> 4) << 3);
    const int bK8  = ((lane >> 3) & 1) * 16;
    const int vRow = (lane & 7) + ((lane >> 3) & 1) * 8;
    const int vColB = (lane >> 4) * 16;

    for (int kt = 0; kt < nkt; kt++) {
        __syncthreads();
        if (kt + 1 < nkt) {
            load_kv(kt + 1, (kt + 1) & 1);
            CP_WAIT(1);
        } else {
            CP_WAIT(0);
        }
        __syncthreads();

        const uint32_t sK = uKV + (kt & 1) * KV_STAGE;
        const uint32_t uK = sK, uV = sK + 9216;

        float s[8][4];
#pragma unroll
        for (int j = 0; j < 8; j++)
#pragma unroll
            for (int e = 0; e < 4; e++) s[j][e] = 0.f;

#pragma unroll
        for (int kk = 0; kk < 4; kk++) {
            uint32_t a0, a1, a2, a3;
            LDMATRIX_X4(a0, a1, a2, a3, uQ + qaddr + kk * 32);
#pragma unroll
            for (int j2 = 0; j2 < 4; j2++) {
                uint32_t r0, r1, r2, r3;
                LDMATRIX_X4(r0, r1, r2, r3,
                            uK + (j2 * 16 + bRow) * AROWB + kk * 32 + bK8);
                MMA_F16(s[2*j2][0], s[2*j2][1], s[2*j2][2], s[2*j2][3],
                        a0, a1, a2, a3, r0, r1);
                MMA_F16(s[2*j2+1][0], s[2*j2+1][1], s[2*j2+1][2], s[2*j2+1][3],
                        a0, a1, a2, a3, r2, r3);
            }
        }

        const int kof = kt * 64 + c * 2;
        float mx0 = -1e30f, mx1 = -1e30f;
#pragma unroll
        for (int j = 0; j < 8; j++) {
            const int ki = kof + j * 8;
            s[j][0] = (ki     < vl0) ? s[j][0] * 0.125f : -1e10f;
            s[j][1] = (ki + 1 < vl0) ? s[j][1] * 0.125f : -1e10f;
            s[j][2] = (ki     < vl1) ? s[j][2] * 0.125f : -1e10f;
            s[j][3] = (ki + 1 < vl1) ? s[j][3] * 0.125f : -1e10f;
            mx0 = fmaxf(mx0, fmaxf(s[j][0], s[j][1]));
            mx1 = fmaxf(mx1, fmaxf(s[j][2], s[j][3]));
        }
        mx0 = fmaxf(mx0, __shfl_xor_sync(0xffffffffu, mx0, 1));
        mx0 = fmaxf(mx0, __shfl_xor_sync(0xffffffffu, mx0, 2));
        mx1 = fmaxf(mx1, __shfl_xor_sync(0xffffffffu, mx1, 1));
        mx1 = fmaxf(mx1, __shfl_xor_sync(0xffffffffu, mx1, 2));

        const float mn0 = fmaxf(m0, mx0), mn1 = fmaxf(m1, mx1);
        const float al_0 = __expf(m0 - mn0), al_1 = __expf(m1 - mn1);
        m0 = mn0; m1 = mn1;

        float rs0 = 0.f, rs1 = 0.f;
#pragma unroll
        for (int j = 0; j < 8; j++) {
            s[j][0] = __expf(s[j][0] - mn0);
            s[j][1] = __expf(s[j][1] - mn0);
            s[j][2] = __expf(s[j][2] - mn1);
            s[j][3] = __expf(s[j][3] - mn1);
            rs0 += s[j][0] + s[j][1];
            rs1 += s[j][2] + s[j][3];
        }
        rs0 += __shfl_xor_sync(0xffffffffu, rs0, 1);
        rs0 += __shfl_xor_sync(0xffffffffu, rs0, 2);
        rs1 += __shfl_xor_sync(0xffffffffu, rs1, 1);
        rs1 += __shfl_xor_sync(0xffffffffu, rs1, 2);
        l0 = l0 * al_0 + rs0;
        l1 = l1 * al_1 + rs1;

#pragma unroll
        for (int j = 0; j < 8; j++) {
            o[j][0] *= al_0; o[j][1] *= al_0;
            o[j][2] *= al_1; o[j][3] *= al_1;
        }

#pragma unroll
        for (int t = 0; t < 4; t++) {
            uint32_t p[4];
            p[0] = packh2(s[2*t][0],   s[2*t][1]);
            p[1] = packh2(s[2*t][2],   s[2*t][3]);
            p[2] = packh2(s[2*t+1][0], s[2*t+1][1]);
            p[3] = packh2(s[2*t+1][2], s[2*t+1][3]);
#pragma unroll
            for (int j2 = 0; j2 < 4; j2++) {
                uint32_t r0, r1, r2, r3;
                LDMATRIX_X4_T(r0, r1, r2, r3,
                              uV + (t * 16 + vRow) * AROWB + j2 * 32 + vColB);
                MMA_F16(o[2*j2][0], o[2*j2][1], o[2*j2][2], o[2*j2][3],
                        p[0], p[1], p[2], p[3], r0, r1);
                MMA_F16(o[2*j2+1][0], o[2*j2+1][1], o[2*j2+1][2], o[2*j2+1][3],
                        p[0], p[1], p[2], p[3], r2, r3);
            }
        }
    }

    const float il0 = 1.0f / l0, il1 = 1.0f / l1;
    const int r0g = b * T_ + q0 + w * 16 + g;
    const int r1g = r0g + 8;
#pragma unroll
    for (int j = 0; j < 8; j++) {
        const int col = h * 64 + j * 8 + c * 2;
        *(uint32_t*)&O[(size_t)r0g * D_ + col] = packh2(o[j][0] * il0, o[j][1] * il0);
        *(uint32_t*)&O[(size_t)r1g * D_ + col] = packh2(o[j][2] * il1, o[j][3] * il1);
    }
}

// ---------------------------------------------------------------------------
// out = LayerNorm(A + Bt) * g + be ; CONV=1 also emits fp16
// ---------------------------------------------------------------------------
template <int CONV>
__global__ void __launch_bounds__(128)
addnorm_kernel(const float* __restrict__ A, const float* __restrict__ Bt,
               const float* __restrict__ g, const float* __restrict__ be,
               float* __restrict__ out, __half* __restrict__ oh)
{
    PDL_TRIGGER();
    PDL_WAIT();
    const int row = blockIdx.x;
    const int tid = threadIdx.x;
    const size_t base = (size_t)row * D_;

    float4 a = *(const float4*)&A[base + tid * 4];
    float4 b = *(const float4*)&Bt[base + tid * 4];
    float4 x = make_float4(a.x + b.x, a.y + b.y, a.z + b.z, a.w + b.w);

    float s  = x.x + x.y + x.z + x.w;
    float sq = x.x * x.x + x.y * x.y + x.z * x.z + x.w * x.w;
#pragma unroll
    for (int off = 16; off; off >>= 1) {
        s  += __shfl_xor_sync(0xffffffffu, s,  off);
        sq += __shfl_xor_sync(0xffffffffu, sq, off);
    }
    __shared__ float ss[4], ssq[4];
    if ((tid & 31) == 0) { ss[tid >> 5] = s; ssq[tid >> 5] = sq; }
    __syncthreads();
    s  = ss[0] + ss[1] + ss[2] + ss[3];
    sq = ssq[0] + ssq[1] + ssq[2] + ssq[3];

    float mu  = s * (1.0f / D_);
    float var = sq * (1.0f / D_) - mu * mu;
    float inv = rsqrtf(var + 1e-5f);

    float4 gg = *(const float4*)&g[tid * 4];
    float4 bb = *(const float4*)&be[tid * 4];
    float4 oo = make_float4((x.x - mu) * inv * gg.x + bb.x,
                            (x.y - mu) * inv * gg.y + bb.y,
                            (x.z - mu) * inv * gg.z + bb.z,
                            (x.w - mu) * inv * gg.w + bb.w);
    *(float4*)&out[base + tid * 4] = oo;
    if (CONV) {
        uint32_t* hp = (uint32_t*)&oh[base + tid * 4];
        hp[0] = packh2(oo.x, oo.y);
        hp[1] = packh2(oo.z, oo.w);
    }
}

// ---------------------------------------------------------------------------
// PDL launch helper
// ---------------------------------------------------------------------------
template <typename... ExpT, typename... ActT>
static void launch_pdl(void (*kern)(ExpT...), dim3 gr, dim3 bl, size_t shm,
                       ActT... args)
{
    cudaLaunchConfig_t cfg = {};
    cfg.gridDim = gr;
    cfg.blockDim = bl;
    cfg.dynamicSmemBytes = shm;
    cfg.stream = 0;
    cudaLaunchAttribute at[1];
    at[0].id = cudaLaunchAttributeProgrammaticStreamSerialization;
    at[0].val.programmaticStreamSerializationAllowed = 1;
    cfg.attrs = at;
    cfg.numAttrs = 1;
    cudaLaunchKernelEx(&cfg, kern, args...);
}

// ---------------------------------------------------------------------------
// Launch
// ---------------------------------------------------------------------------
extern "C" void kernel_launch(void* const* d_in, const int* in_sizes, int n_in,
                              void* d_out, int out_size)
{
    const float* X    = (const float*)d_in[0];
    const float* ENC  = (const float*)d_in[1];
    const int*   DVL  = (const int*)d_in[2];
    const int*   EVL  = (const int*)d_in[3];
    const float* Wmat[8] = {
        (const float*)d_in[4],  (const float*)d_in[5],
        (const float*)d_in[6],  (const float*)d_in[7],
        (const float*)d_in[8],  (const float*)d_in[9],
        (const float*)d_in[10], (const float*)d_in[11]};
    const float* W1   = (const float*)d_in[12];
    const float* b1   = (const float*)d_in[13];
    const float* W2   = (const float*)d_in[14];
    const float* b2   = (const float*)d_in[15];
    const float* G1   = (const float*)d_in[16];
    const float* BE1  = (const float*)d_in[17];
    const float* G2   = (const float*)d_in[18];
    const float* BE2  = (const float*)d_in[19];
    const float* G3   = (const float*)d_in[20];
    const float* BE3  = (const float*)d_in[21];
    float* out = (float*)d_out;

    float *tmp, *Y, *Z;
    __half *x1, *x2, *qkv, *kv, *q2, *at, *Fb, *Wb;
    cudaGetSymbolAddress((void**)&tmp, g_tmp);
    cudaGetSymbolAddress((void**)&Y,   g_Y);
    cudaGetSymbolAddress((void**)&Z,   g_Z);
    cudaGetSymbolAddress((void**)&x1,  g_x1);
    cudaGetSymbolAddress((void**)&x2,  g_x2);
    cudaGetSymbolAddress((void**)&qkv, g_qkv);
    cudaGetSymbolAddress((void**)&kv,  g_kv);
    cudaGetSymbolAddress((void**)&q2,  g_q2);
    cudaGetSymbolAddress((void**)&at,  g_at);
    cudaGetSymbolAddress((void**)&Fb,  g_F);
    cudaGetSymbolAddress((void**)&Wb,  g_W);

    cudaFuncSetAttribute(attn_hmma,
                         cudaFuncAttributeMaxDynamicSharedMemorySize, ATT_SMEM);
    cudaFuncSetAttribute(gemm_hmma<0, 0, 1>,
                         cudaFuncAttributeMaxDynamicSharedMemorySize, GEMM_SMEM);
    cudaFuncSetAttribute(gemm_hmma<0, 0, 0>,
                         cudaFuncAttributeMaxDynamicSharedMemorySize, GEMM_SMEM);
    cudaFuncSetAttribute(gemm_hmma<1, 1, 1>,
                         cudaFuncAttributeMaxDynamicSharedMemorySize, GEMM_SMEM);
    cudaFuncSetAttribute(gemm_hmma<1, 0, 0>,
                         cudaFuncAttributeMaxDynamicSharedMemorySize, GEMM_SMEM);
    cudaFuncSetAttribute(gemm_dual,
                         cudaFuncAttributeMaxDynamicSharedMemorySize, GEMM_SMEM);

    size_t WO[10];
    for (int i = 0; i < 8; i++) WO[i] = (size_t)i * D_ * D_;
    WO[8] = 8ull * D_ * D_;
    WO[9] = WO[8] + (size_t)F_ * D_;

    const int nDD = D_ * D_ / 4;       // 65536
    const int nMD = M_ * D_ / 4;       // 2097152
    const int nFD = F_ * D_ / 4;       // 262144

    ConvSegs segs;
    int total4 = 0;
    for (int i = 0; i < 8; i++) {
        segs.src[i] = Wmat[i];
        segs.dst[i] = Wb + WO[i];
        segs.n4[i] = nDD; total4 += nDD;
    }
    segs.src[8] = W1; segs.dst[8] = Wb + WO[8]; segs.n4[8] = nFD; total4 += nFD;
    segs.src[9] = W2; segs.dst[9] = Wb + WO[9]; segs.n4[9] = nFD; total4 += nFD;
    segs.src[10] = X;   segs.dst[10] = x1; segs.n4[10] = nMD; total4 += nMD;
    segs.src[11] = ENC; segs.dst[11] = x2; segs.n4[11] = nMD; total4 += nMD;
    launch_pdl(mconv_kernel, dim3((total4 + 255) / 256), dim3(256), 0, segs);

    dim3 gQKV(1536 / 128, M_ / 128);   // (12, 128)
    dim3 gDUO(12,         M_ / 128);   // q2(4) + kv(8)
    dim3 gP  (D_ / 128,   M_ / 128);   // (4, 128)
    dim3 gF1 (F_ / 128,   M_ / 128);   // (16, 128)
    dim3 gA  (B_ * H_,    T_ / 128);   // (256, 4)
    dim3 gAN (M_);

    // ---- self-attention ----
    launch_pdl(gemm_hmma<0,0,1>, gQKV, dim3(256), GEMM_SMEM,
               (const __half*)x1, (const __half*)(Wb + WO[0]),
               (const float*)nullptr, (float*)nullptr, qkv, 1536, D_);
    launch_pdl(attn_hmma, gA, dim3(256), (size_t)ATT_SMEM,
               (const __half*)qkv, 1536,
               (const __half*)(qkv + 512), (const __half*)(qkv + 1024), 1536,
               DVL, 1, at);
    launch_pdl(gemm_hmma<0,0,0>, gP, dim3(256), GEMM_SMEM,
               (const __half*)at, (const __half*)(Wb + WO[3]),
               (const float*)nullptr, tmp, (__half*)nullptr, D_, D_);
    launch_pdl(addnorm_kernel<1>, gAN, dim3(128), 0,
               X, (const float*)tmp, G1, BE1, Y, x1);

    // ---- cross-attention (Q2 + KV in one launch) ----
    launch_pdl(gemm_dual, gDUO, dim3(256), GEMM_SMEM,
               (const __half*)x1, (const __half*)(Wb + WO[4]), q2, 512, 4,
               (const __half*)x2, (const __half*)(Wb + WO[5]), kv, 1024, D_);
    launch_pdl(attn_hmma, gA, dim3(256), (size_t)ATT_SMEM,
               (const __half*)q2, D_,
               (const __half*)kv, (const __half*)(kv + 512), 1024,
               EVL, 0, at);
    launch_pdl(gemm_hmma<0,0,0>, gP, dim3(256), GEMM_SMEM,
               (const __half*)at, (const __half*)(Wb + WO[7]),
               (const float*)nullptr, tmp, (__half*)nullptr, D_, D_);
    launch_pdl(addnorm_kernel<1>, gAN, dim3(128), 0,
               (const float*)Y, (const float*)tmp, G2, BE2, Z, x2);

    // ---- FFN ----
    launch_pdl(gemm_hmma<1,1,1>, gF1, dim3(256), GEMM_SMEM,
               (const __half*)x2, (const __half*)(Wb + WO[8]),
               b1, (float*)nullptr, Fb, F_, D_);
    launch_pdl(gemm_hmma<1,0,0>, gP, dim3(256), GEMM_SMEM,
               (const __half*)Fb, (const __half*)(Wb + WO[9]),
               b2, tmp, (__half*)nullptr, D_, F_);
    launch_pdl(addnorm_kernel<0>, gAN, dim3(128), 0,
               (const float*)Z, (const float*)tmp, G3, BE3, out,
               (__half*)nullptr);
}

// round 15
// speedup vs baseline: 2.3842x; 1.0007x over previous
#include <cuda_runtime.h>
#include <cuda_fp16.h>
#include <math.h>
#include <stdint.h>

// Problem constants
#define B_ 32
#define T_ 512
#define D_ 512
#define H_ 8
#define M_ (B_ * T_)   // 16384 rows
#define F_ 2048

// ---------------------------------------------------------------------------
// Scratch (device globals; no allocation allowed)
// ---------------------------------------------------------------------------
__device__ float g_tmp[(size_t)M_ * D_];
__device__ float g_Y  [(size_t)M_ * D_];
__device__ float g_Z  [(size_t)M_ * D_];

__device__ __half g_x1 [(size_t)M_ * D_];     // X / Y (fp16)
__device__ __half g_x2 [(size_t)M_ * D_];     // ENC / Z (fp16)
__device__ __half g_qkv[(size_t)M_ * 1536];   // self QKV fused
__device__ __half g_kv [(size_t)M_ * 1024];   // cross KV fused
__device__ __half g_q2 [(size_t)M_ * D_];     // cross Q
__device__ __half g_at [(size_t)M_ * D_];     // attention output
__device__ __half g_F  [(size_t)M_ * F_];     // FFN intermediate
__device__ __half g_W  [4194304];             // all weights fp16

// ---------------------------------------------------------------------------
// helpers
// ---------------------------------------------------------------------------
__device__ __forceinline__ uint32_t smem_u32(const void* p) {
    uint32_t a;
    asm("{ .reg .u64 t; cvta.to.shared.u64 t, %1; cvt.u32.u64 %0, t; }"
        : "=r"(a) : "l"(p));
    return a;
}

#define PDL_TRIGGER() asm volatile("griddepcontrol.launch_dependents;" ::: "memory")
#define PDL_WAIT()    asm volatile("griddepcontrol.wait;" ::: "memory")

#define CP_ASYNC16(dst, src) \
    asm volatile("cp.async.cg.shared.global [%0], [%1], 16;" :: \
                 "r"(dst), "l"(src) : "memory")
#define CP_COMMIT() asm volatile("cp.async.commit_group;" ::: "memory")
#define CP_WAIT(n)  asm volatile("cp.async.wait_group %0;" :: "n"(n) : "memory")

#define LDMATRIX_X4(r0, r1, r2, r3, addr) \
    asm volatile("ldmatrix.sync.aligned.m8n8.x4.shared.b16 {%0,%1,%2,%3}, [%4];" \
                 : "=r"(r0), "=r"(r1), "=r"(r2), "=r"(r3) : "r"(addr))

#define LDMATRIX_X4_T(r0, r1, r2, r3, addr) \
    asm volatile("ldmatrix.sync.aligned.m8n8.x4.trans.shared.b16 {%0,%1,%2,%3}, [%4];" \
                 : "=r"(r0), "=r"(r1), "=r"(r2), "=r"(r3) : "r"(addr))

#define MMA_F16(d0, d1, d2, d3, a0, a1, a2, a3, b0, b1) \
    asm volatile("mma.sync.aligned.m16n8k16.row.col.f32.f16.f16.f32 " \
                 "{%0,%1,%2,%3}, {%4,%5,%6,%7}, {%8,%9}, {%0,%1,%2,%3};" \
                 : "+f"(d0), "+f"(d1), "+f"(d2), "+f"(d3) \
                 : "r"(a0), "r"(a1), "r"(a2), "r"(a3), "r"(b0), "r"(b1))

__device__ __forceinline__ uint32_t packh2(float x, float y) {
    __half2 h = __floats2half2_rn(x, y);
    return *reinterpret_cast<uint32_t*>(&h);
}

// ---------------------------------------------------------------------------
// merged convert fp32 -> fp16: 12 segments in one launch
// ---------------------------------------------------------------------------
struct ConvSegs {
    const float* src[12];
    __half* dst[12];
    int n4[12];
};

__global__ void __launch_bounds__(256)
mconv_kernel(ConvSegs s)
{
    PDL_TRIGGER();
    int i = blockIdx.x * 256 + threadIdx.x;
#pragma unroll
    for (int k = 0; k < 12; k++) {
        if (i < s.n4[k]) {
            float4 v = ((const float4*)s.src[k])[i];
            uint32_t* dp = (uint32_t*)s.dst[k];
            dp[2 * i]     = packh2(v.x, v.y);
            dp[2 * i + 1] = packh2(v.z, v.w);
            return;
        }
        i -= s.n4[k];
    }
}

// ---------------------------------------------------------------------------
// fp16 HMMA GEMM: C[M,N] = A[M,K] @ W[N,K]^T (single pass, fp32 accum)
// 128x128 CTA tile, 256 threads, 8 warps (2 M x 4 N), warp tile 64x32.
// K-chunk = 64 (two 32-col sub-tiles per stage) -> 64 MMA per barrier.
// XOR-swizzled 64B-row SMEM, 3-stage cp.async pipeline (prefetch dist 2).
// ---------------------------------------------------------------------------
#define TILE_H 8192                  // 128 rows x 32 fp16 = 8 KB sub-tile
#define STAGE_B (4 * TILE_H)         // A0, A1, W0, W1 = 32768
#define GEMM_SMEM (3 * STAGE_B)      // 98304

template <int BIAS, int LEAKY, int CONV>
__device__ __forceinline__ void gemm_body(
    const __half* __restrict__ A, const __half* __restrict__ W,
    const float* __restrict__ bias, float* __restrict__ C,
    __half* __restrict__ Ch,
    int N, int K, int bm, int bn, char* smem)
{
    PDL_TRIGGER();
    const uint32_t sbase = smem_u32(smem);

    const int tid = threadIdx.x;
    const int wid = tid >> 5, lane = tid & 31;
    const int wm = wid & 1, wn = wid >> 1;     // 2 M x 4 N warp grid

    const int ldr0 = tid >> 2;            // row 0..63
    const int ldc4 = tid & 3;             // 16B-chunk 0..3
    const int ldce = ldc4 * 8;            // element col within sub-tile

    const __half* gA = A + (size_t)(bm + ldr0) * K + ldce;
    const __half* gW = W + (size_t)(bn + ldr0) * K + ldce;
    const size_t rstep = (size_t)64 * K;

    uint32_t sro[2];
#pragma unroll
    for (int h = 0; h < 2; h++) {
        const int r = ldr0 + h * 64;
        sro[h] = (uint32_t)(r * 64 + ((ldc4 ^ ((r >> 1) & 3)) << 4));
    }

    const int aRowB = wm * 64 + (lane & 15);
    const int aKc0  = (lane >> 4);
    const int aSw   = (aRowB >> 1) & 3;
    const int bRowB = wn * 32 + (lane & 7) + ((lane >> 4) << 3);
    const int bKc0  = (lane >> 3) & 1;
    const int bSw   = (bRowB >> 1) & 3;

    float acc[4][4][4];
#pragma unroll
    for (int i = 0; i < 4; i++)
#pragma unroll
        for (int j = 0; j < 4; j++)
#pragma unroll
            for (int r = 0; r < 4; r++) acc[i][j][r] = 0.f;

    const int NC = K >> 6;   // chunks of 64

    auto load_chunk = [&](int c, int buf) {
        const uint32_t st = sbase + buf * STAGE_B;
        const int koff = c << 6;
#pragma unroll
        for (int h = 0; h < 2; h++) {
            // A sub-tiles: cols [koff, koff+32) and [koff+32, koff+64)
            CP_ASYNC16(st + sro[h],              gA + (size_t)h * rstep + koff);
            CP_ASYNC16(st + TILE_H + sro[h],     gA + (size_t)h * rstep + koff + 32);
            CP_ASYNC16(st + 2 * TILE_H + sro[h], gW + (size_t)h * rstep + koff);
            CP_ASYNC16(st + 3 * TILE_H + sro[h], gW + (size_t)h * rstep + koff + 32);
        }
        CP_COMMIT();
    };

    PDL_WAIT();
    load_chunk(0, 0);
    load_chunk(1, 1);
    int lbuf = 2, cbuf = 0;

    for (int c = 0; c < NC; c++) {
        if (c + 1 < NC) { CP_WAIT(1); } else { CP_WAIT(0); }
        __syncthreads();
        if (c + 2 < NC) {
            load_chunk(c + 2, lbuf);
            lbuf = (lbuf == 2) ? 0 : lbuf + 1;
        }

        const uint32_t st = sbase + cbuf * STAGE_B;
        cbuf = (cbuf == 2) ? 0 : cbuf + 1;

#pragma unroll
        for (int sub = 0; sub < 2; sub++) {
            const uint32_t aB = st + sub * TILE_H;
            const uint32_t bB = st + (2 + sub) * TILE_H;
#pragma unroll
            for (int ks = 0; ks < 2; ks++) {
                const uint32_t aoff = (uint32_t)(aRowB * 64 +
                                      (((ks * 2 + aKc0) ^ aSw) << 4));
                const uint32_t boff = (uint32_t)(bRowB * 64 +
                                      (((ks * 2 + bKc0) ^ bSw) << 4));

                uint32_t b[4][2];
#pragma unroll
                for (int j2 = 0; j2 < 2; j2++) {
                    uint32_t r0, r1, r2, r3;
                    LDMATRIX_X4(r0, r1, r2, r3, bB + boff + j2 * 1024);
                    b[j2 * 2 + 0][0] = r0; b[j2 * 2 + 0][1] = r1;
                    b[j2 * 2 + 1][0] = r2; b[j2 * 2 + 1][1] = r3;
                }
                uint32_t a[4][4];
#pragma unroll
                for (int i = 0; i < 4; i++)
                    LDMATRIX_X4(a[i][0], a[i][1], a[i][2], a[i][3],
                                aB + aoff + i * 1024);
#pragma unroll
                for (int i = 0; i < 4; i++)
#pragma unroll
                    for (int j = 0; j < 4; j++)
                        MMA_F16(acc[i][j][0], acc[i][j][1], acc[i][j][2], acc[i][j][3],
                                a[i][0], a[i][1], a[i][2], a[i][3], b[j][0], b[j][1]);
            }
        }
    }

    const int tg = lane >> 2;
    const int tc = (lane & 3) * 2;
#pragma unroll
    for (int i = 0; i < 4; i++) {
        const int r0 = bm + wm * 64 + i * 16 + tg;
#pragma unroll
        for (int j = 0; j < 4; j++) {
            const int col = bn + wn * 32 + j * 8 + tc;
            float v0 = acc[i][j][0], v1 = acc[i][j][1];
            float v2 = acc[i][j][2], v3 = acc[i][j][3];
            if (BIAS) {
                const float b0 = bias[col], b1 = bias[col + 1];
                v0 += b0; v1 += b1; v2 += b0; v3 += b1;
            }
            if (LEAKY) {
                v0 = v0 > 0.f ? v0 : 0.01f * v0;
                v1 = v1 > 0.f ? v1 : 0.01f * v1;
                v2 = v2 > 0.f ? v2 : 0.01f * v2;
                v3 = v3 > 0.f ? v3 : 0.01f * v3;
            }
            if (CONV) {
                *(uint32_t*)&Ch[(size_t)r0 * N + col]       = packh2(v0, v1);
                *(uint32_t*)&Ch[(size_t)(r0 + 8) * N + col] = packh2(v2, v3);
            } else {
                *(float2*)&C[(size_t)r0 * N + col]       = make_float2(v0, v1);
                *(float2*)&C[(size_t)(r0 + 8) * N + col] = make_float2(v2, v3);
            }
        }
    }
}

template <int BIAS, int LEAKY, int CONV>
__global__ void __launch_bounds__(256, 2)
gemm_hmma(const __half* __restrict__ A, const __half* __restrict__ W,
          const float* __restrict__ bias, float* __restrict__ C,
          __half* __restrict__ Ch, int N, int K)
{
    extern __shared__ __align__(16) char smem[];
    gemm_body<BIAS, LEAKY, CONV>(A, W, bias, C, Ch,
                                 N, K, blockIdx.y * 128, blockIdx.x * 128, smem);
}

// Two independent fp16-out GEMM jobs in one launch (cross-attn Q2 + KV)
__global__ void __launch_bounds__(256, 2)
gemm_dual(const __half* A0, const __half* W0, __half* C0, int N0, int nb0,
          const __half* A1, const __half* W1, __half* C1, int N1, int K)
{
    extern __shared__ __align__(16) char smem[];
    if ((int)blockIdx.x < nb0)
        gemm_body<0, 0, 1>(A0, W0, nullptr, nullptr, C0,
                           N0, K, blockIdx.y * 128, blockIdx.x * 128, smem);
    else
        gemm_body<0, 0, 1>(A1, W1, nullptr, nullptr, C1,
                           N1, K, blockIdx.y * 128, (blockIdx.x - nb0) * 128, smem);
}

// ---------------------------------------------------------------------------
// fp16 HMMA flash attention (single pass), cp.async 2-stage K/V pipeline.
// ---------------------------------------------------------------------------
#define AROWB 144
#define KV_STAGE 18432                       // K (64x144) + V (64x144)
#define ATT_SMEM (18432 + 2 * KV_STAGE)      // Q + 2 stages = 55296

__global__ void __launch_bounds__(256, 2)
attn_hmma(const __half* __restrict__ Q, int qs,
          const __half* __restrict__ K, const __half* __restrict__ V, int kvs,
          const int* __restrict__ vlp, int per_row,
          __half* __restrict__ O)
{
    PDL_TRIGGER();
    extern __shared__ __align__(16) char sm[];
    char* cQ = sm;
    const uint32_t uQ  = smem_u32(cQ);
    const uint32_t uKV = smem_u32(sm + 18432);
    __shared__ int sred[8];

    const int tid = threadIdx.x;
    const int w = tid >> 5, lane = tid & 31;
    const int g = lane >> 2, c = lane & 3;
    const int b = blockIdx.x >> 3, h = blockIdx.x & 7;
    const int q0 = blockIdx.y * 128;

    int kmax;
    if (per_row) {
        int v = (tid < 128) ? vlp[b * T_ + q0 + tid] : 0;
#pragma unroll
        for (int off = 16; off; off >>= 1)
            v = max(v, __shfl_xor_sync(0xffffffffu, v, off));
        if (lane == 0) sred[w] = v;
        __syncthreads();
        kmax = sred[0];
#pragma unroll
        for (int i = 1; i < 8; i++) kmax = max(kmax, sred[i]);
    } else {
        kmax = vlp[b];
    }
    const int nkt = (kmax + 63) >> 6;

    int vl0, vl1;
    if (per_row) {
        vl0 = vlp[b * T_ + q0 + w * 16 + g];
        vl1 = vlp[b * T_ + q0 + w * 16 + g + 8];
    } else {
        vl0 = vl1 = kmax;
    }

    PDL_WAIT();

    const __half* qp = Q + (size_t)(b * T_ + q0) * qs + h * 64;
    for (int i = tid; i < 1024; i += 256) {
        const int r = i >> 3, ch = i & 7;
        *(uint4*)(cQ + r * AROWB + ch * 16) =
            *(const uint4*)(qp + (size_t)r * qs + ch * 8);
    }

    auto load_kv = [&](int kt, int stg) {
        const size_t kb = (size_t)(b * T_ + kt * 64) * kvs + h * 64;
        const uint32_t sb = uKV + stg * KV_STAGE;
        for (int i = tid; i < 512; i += 256) {
            const int r = i >> 3, ch = i & 7;
            const size_t go = kb + (size_t)r * kvs + ch * 8;
            const uint32_t so = r * AROWB + ch * 16;
            CP_ASYNC16(sb + so,        K + go);
            CP_ASYNC16(sb + 9216 + so, V + go);
        }
        CP_COMMIT();
    };
    load_kv(0, 0);

    float m0 = -1e30f, m1 = -1e30f, l0 = 0.f, l1 = 0.f;
    float o[8][4];
#pragma unroll
    for (int j = 0; j < 8; j++)
#pragma unroll
        for (int e = 0; e < 4; e++) o[j][e] = 0.f;

    const uint32_t qaddr = (w * 16 + (lane & 15)) * AROWB + (lane >> 4) * 16;
    const int bRow = (lane & 7) + ((lane >> 4) << 3);
    const int bK8  = ((lane >> 3) & 1) * 16;
    const int vRow = (lane & 7) + ((lane >> 3) & 1) * 8;
    const int vColB = (lane >> 4) * 16;

    for (int kt = 0; kt < nkt; kt++) {
        __syncthreads();
        if (kt + 1 < nkt) {
            load_kv(kt + 1, (kt + 1) & 1);
            CP_WAIT(1);
        } else {
            CP_WAIT(0);
        }
        __syncthreads();

        const uint32_t sK = uKV + (kt & 1) * KV_STAGE;
        const uint32_t uK = sK, uV = sK + 9216;

        float s[8][4];
#pragma unroll
        for (int j = 0; j < 8; j++)
#pragma unroll
            for (int e = 0; e < 4; e++) s[j][e] = 0.f;

#pragma unroll
        for (int kk = 0; kk < 4; kk++) {
            uint32_t a0, a1, a2, a3;
            LDMATRIX_X4(a0, a1, a2, a3, uQ + qaddr + kk * 32);
#pragma unroll
            for (int j2 = 0; j2 < 4; j2++) {
                uint32_t r0, r1, r2, r3;
                LDMATRIX_X4(r0, r1, r2, r3,
                            uK + (j2 * 16 + bRow) * AROWB + kk * 32 + bK8);
                MMA_F16(s[2*j2][0], s[2*j2][1], s[2*j2][2], s[2*j2][3],
                        a0, a1, a2, a3, r0, r1);
                MMA_F16(s[2*j2+1][0], s[2*j2+1][1], s[2*j2+1][2], s[2*j2+1][3],
                        a0, a1, a2, a3, r2, r3);
            }
        }

        const int kof = kt * 64 + c * 2;
        float mx0 = -1e30f, mx1 = -1e30f;
#pragma unroll
        for (int j = 0; j < 8; j++) {
            const int ki = kof + j * 8;
            s[j][0] = (ki     < vl0) ? s[j][0] * 0.125f : -1e10f;
            s[j][1] = (ki + 1 < vl0) ? s[j][1] * 0.125f : -1e10f;
            s[j][2] = (ki     < vl1) ? s[j][2] * 0.125f : -1e10f;
            s[j][3] = (ki + 1 < vl1) ? s[j][3] * 0.125f : -1e10f;
            mx0 = fmaxf(mx0, fmaxf(s[j][0], s[j][1]));
            mx1 = fmaxf(mx1, fmaxf(s[j][2], s[j][3]));
        }
        mx0 = fmaxf(mx0, __shfl_xor_sync(0xffffffffu, mx0, 1));
        mx0 = fmaxf(mx0, __shfl_xor_sync(0xffffffffu, mx0, 2));
        mx1 = fmaxf(mx1, __shfl_xor_sync(0xffffffffu, mx1, 1));
        mx1 = fmaxf(mx1, __shfl_xor_sync(0xffffffffu, mx1, 2));

        const float mn0 = fmaxf(m0, mx0), mn1 = fmaxf(m1, mx1);
        const float al_0 = __expf(m0 - mn0), al_1 = __expf(m1 - mn1);
        m0 = mn0; m1 = mn1;

        float rs0 = 0.f, rs1 = 0.f;
#pragma unroll
        for (int j = 0; j < 8; j++) {
            s[j][0] = __expf(s[j][0] - mn0);
            s[j][1] = __expf(s[j][1] - mn0);
            s[j][2] = __expf(s[j][2] - mn1);
            s[j][3] = __expf(s[j][3] - mn1);
            rs0 += s[j][0] + s[j][1];
            rs1 += s[j][2] + s[j][3];
        }
        rs0 += __shfl_xor_sync(0xffffffffu, rs0, 1);
        rs0 += __shfl_xor_sync(0xffffffffu, rs0, 2);
        rs1 += __shfl_xor_sync(0xffffffffu, rs1, 1);
        rs1 += __shfl_xor_sync(0xffffffffu, rs1, 2);
        l0 = l0 * al_0 + rs0;
        l1 = l1 * al_1 + rs1;

#pragma unroll
        for (int j = 0; j < 8; j++) {
            o[j][0] *= al_0; o[j][1] *= al_0;
            o[j][2] *= al_1; o[j][3] *= al_1;
        }

#pragma unroll
        for (int t = 0; t < 4; t++) {
            uint32_t p[4];
            p[0] = packh2(s[2*t][0],   s[2*t][1]);
            p[1] = packh2(s[2*t][2],   s[2*t][3]);
            p[2] = packh2(s[2*t+1][0], s[2*t+1][1]);
            p[3] = packh2(s[2*t+1][2], s[2*t+1][3]);
#pragma unroll
            for (int j2 = 0; j2 < 4; j2++) {
                uint32_t r0, r1, r2, r3;
                LDMATRIX_X4_T(r0, r1, r2, r3,
                              uV + (t * 16 + vRow) * AROWB + j2 * 32 + vColB);
                MMA_F16(o[2*j2][0], o[2*j2][1], o[2*j2][2], o[2*j2][3],
                        p[0], p[1], p[2], p[3], r0, r1);
                MMA_F16(o[2*j2+1][0], o[2*j2+1][1], o[2*j2+1][2], o[2*j2+1][3],
                        p[0], p[1], p[2], p[3], r2, r3);
            }
        }
    }

    const float il0 = 1.0f / l0, il1 = 1.0f / l1;
    const int r0g = b * T_ + q0 + w * 16 + g;
    const int r1g = r0g + 8;
#pragma unroll
    for (int j = 0; j < 8; j++) {
        const int col = h * 64 + j * 8 + c * 2;
        *(uint32_t*)&O[(size_t)r0g * D_ + col] = packh2(o[j][0] * il0, o[j][1] * il0);
        *(uint32_t*)&O[(size_t)r1g * D_ + col] = packh2(o[j][2] * il1, o[j][3] * il1);
    }
}

// ---------------------------------------------------------------------------
// out = LayerNorm(A + Bt) * g + be ; CONV=1 also emits fp16
// ---------------------------------------------------------------------------
template <int CONV>
__global__ void __launch_bounds__(128)
addnorm_kernel(const float* __restrict__ A, const float* __restrict__ Bt,
               const float* __restrict__ g, const float* __restrict__ be,
               float* __restrict__ out, __half* __restrict__ oh)
{
    PDL_TRIGGER();
    PDL_WAIT();
    const int row = blockIdx.x;
    const int tid = threadIdx.x;
    const size_t base = (size_t)row * D_;

    float4 a = *(const float4*)&A[base + tid * 4];
    float4 b = *(const float4*)&Bt[base + tid * 4];
    float4 x = make_float4(a.x + b.x, a.y + b.y, a.z + b.z, a.w + b.w);

    float s  = x.x + x.y + x.z + x.w;
    float sq = x.x * x.x + x.y * x.y + x.z * x.z + x.w * x.w;
#pragma unroll
    for (int off = 16; off; off >>= 1) {
        s  += __shfl_xor_sync(0xffffffffu, s,  off);
        sq += __shfl_xor_sync(0xffffffffu, sq, off);
    }
    __shared__ float ss[4], ssq[4];
    if ((tid & 31) == 0) { ss[tid >> 5] = s; ssq[tid >> 5] = sq; }
    __syncthreads();
    s  = ss[0] + ss[1] + ss[2] + ss[3];
    sq = ssq[0] + ssq[1] + ssq[2] + ssq[3];

    float mu  = s * (1.0f / D_);
    float var = sq * (1.0f / D_) - mu * mu;
    float inv = rsqrtf(var + 1e-5f);

    float4 gg = *(const float4*)&g[tid * 4];
    float4 bb = *(const float4*)&be[tid * 4];
    float4 oo = make_float4((x.x - mu) * inv * gg.x + bb.x,
                            (x.y - mu) * inv * gg.y + bb.y,
                            (x.z - mu) * inv * gg.z + bb.z,
                            (x.w - mu) * inv * gg.w + bb.w);
    *(float4*)&out[base + tid * 4] = oo;
    if (CONV) {
        uint32_t* hp = (uint32_t*)&oh[base + tid * 4];
        hp[0] = packh2(oo.x, oo.y);
        hp[1] = packh2(oo.z, oo.w);
    }
}

// ---------------------------------------------------------------------------
// PDL launch helper
// ---------------------------------------------------------------------------
template <typename... ExpT, typename... ActT>
static void launch_pdl(void (*kern)(ExpT...), dim3 gr, dim3 bl, size_t shm,
                       ActT... args)
{
    cudaLaunchConfig_t cfg = {};
    cfg.gridDim = gr;
    cfg.blockDim = bl;
    cfg.dynamicSmemBytes = shm;
    cfg.stream = 0;
    cudaLaunchAttribute at[1];
    at[0].id = cudaLaunchAttributeProgrammaticStreamSerialization;
    at[0].val.programmaticStreamSerializationAllowed = 1;
    cfg.attrs = at;
    cfg.numAttrs = 1;
    cudaLaunchKernelEx(&cfg, kern, args...);
}

// ---------------------------------------------------------------------------
// Launch
// ---------------------------------------------------------------------------
extern "C" void kernel_launch(void* const* d_in, const int* in_sizes, int n_in,
                              void* d_out, int out_size)
{
    const float* X    = (const float*)d_in[0];
    const float* ENC  = (const float*)d_in[1];
    const int*   DVL  = (const int*)d_in[2];
    const int*   EVL  = (const int*)d_in[3];
    const float* Wmat[8] = {
        (const float*)d_in[4],  (const float*)d_in[5],
        (const float*)d_in[6],  (const float*)d_in[7],
        (const float*)d_in[8],  (const float*)d_in[9],
        (const float*)d_in[10], (const float*)d_in[11]};
    const float* W1   = (const float*)d_in[12];
    const float* b1   = (const float*)d_in[13];
    const float* W2   = (const float*)d_in[14];
    const float* b2   = (const float*)d_in[15];
    const float* G1   = (const float*)d_in[16];
    const float* BE1  = (const float*)d_in[17];
    const float* G2   = (const float*)d_in[18];
    const float* BE2  = (const float*)d_in[19];
    const float* G3   = (const float*)d_in[20];
    const float* BE3  = (const float*)d_in[21];
    float* out = (float*)d_out;

    float *tmp, *Y, *Z;
    __half *x1, *x2, *qkv, *kv, *q2, *at, *Fb, *Wb;
    cudaGetSymbolAddress((void**)&tmp, g_tmp);
    cudaGetSymbolAddress((void**)&Y,   g_Y);
    cudaGetSymbolAddress((void**)&Z,   g_Z);
    cudaGetSymbolAddress((void**)&x1,  g_x1);
    cudaGetSymbolAddress((void**)&x2,  g_x2);
    cudaGetSymbolAddress((void**)&qkv, g_qkv);
    cudaGetSymbolAddress((void**)&kv,  g_kv);
    cudaGetSymbolAddress((void**)&q2,  g_q2);
    cudaGetSymbolAddress((void**)&at,  g_at);
    cudaGetSymbolAddress((void**)&Fb,  g_F);
    cudaGetSymbolAddress((void**)&Wb,  g_W);

    cudaFuncSetAttribute(attn_hmma,
                         cudaFuncAttributeMaxDynamicSharedMemorySize, ATT_SMEM);
    cudaFuncSetAttribute(gemm_hmma<0, 0, 1>,
                         cudaFuncAttributeMaxDynamicSharedMemorySize, GEMM_SMEM);
    cudaFuncSetAttribute(gemm_hmma<0, 0, 0>,
                         cudaFuncAttributeMaxDynamicSharedMemorySize, GEMM_SMEM);
    cudaFuncSetAttribute(gemm_hmma<1, 1, 1>,
                         cudaFuncAttributeMaxDynamicSharedMemorySize, GEMM_SMEM);
    cudaFuncSetAttribute(gemm_hmma<1, 0, 0>,
                         cudaFuncAttributeMaxDynamicSharedMemorySize, GEMM_SMEM);
    cudaFuncSetAttribute(gemm_dual,
                         cudaFuncAttributeMaxDynamicSharedMemorySize, GEMM_SMEM);

    size_t WO[10];
    for (int i = 0; i < 8; i++) WO[i] = (size_t)i * D_ * D_;
    WO[8] = 8ull * D_ * D_;
    WO[9] = WO[8] + (size_t)F_ * D_;

    const int nDD = D_ * D_ / 4;       // 65536
    const int nMD = M_ * D_ / 4;       // 2097152
    const int nFD = F_ * D_ / 4;       // 262144

    ConvSegs segs;
    int total4 = 0;
    for (int i = 0; i < 8; i++) {
        segs.src[i] = Wmat[i];
        segs.dst[i] = Wb + WO[i];
        segs.n4[i] = nDD; total4 += nDD;
    }
    segs.src[8] = W1; segs.dst[8] = Wb + WO[8]; segs.n4[8] = nFD; total4 += nFD;
    segs.src[9] = W2; segs.dst[9] = Wb + WO[9]; segs.n4[9] = nFD; total4 += nFD;
    segs.src[10] = X;   segs.dst[10] = x1; segs.n4[10] = nMD; total4 += nMD;
    segs.src[11] = ENC; segs.dst[11] = x2; segs.n4[11] = nMD; total4 += nMD;
    launch_pdl(mconv_kernel, dim3((total4 + 255) / 256), dim3(256), 0, segs);

    dim3 gQKV(1536 / 128, M_ / 128);   // (12, 128)
    dim3 gDUO(12,         M_ / 128);   // q2(4) + kv(8)
    dim3 gP  (D_ / 128,   M_ / 128);   // (4, 128)
    dim3 gF1 (F_ / 128,   M_ / 128);   // (16, 128)
    dim3 gA  (B_ * H_,    T_ / 128);   // (256, 4)
    dim3 gAN (M_);

    // ---- self-attention ----
    launch_pdl(gemm_hmma<0,0,1>, gQKV, dim3(256), GEMM_SMEM,
               (const __half*)x1, (const __half*)(Wb + WO[0]),
               (const float*)nullptr, (float*)nullptr, qkv, 1536, D_);
    launch_pdl(attn_hmma, gA, dim3(256), (size_t)ATT_SMEM,
               (const __half*)qkv, 1536,
               (const __half*)(qkv + 512), (const __half*)(qkv + 1024), 1536,
               DVL, 1, at);
    launch_pdl(gemm_hmma<0,0,0>, gP, dim3(256), GEMM_SMEM,
               (const __half*)at, (const __half*)(Wb + WO[3]),
               (const float*)nullptr, tmp, (__half*)nullptr, D_, D_);
    launch_pdl(addnorm_kernel<1>, gAN, dim3(128), 0,
               X, (const float*)tmp, G1, BE1, Y, x1);

    // ---- cross-attention (Q2 + KV in one launch) ----
    launch_pdl(gemm_dual, gDUO, dim3(256), GEMM_SMEM,
               (const __half*)x1, (const __half*)(Wb + WO[4]), q2, 512, 4,
               (const __half*)x2, (const __half*)(Wb + WO[5]), kv, 1024, D_);
    launch_pdl(attn_hmma, gA, dim3(256), (size_t)ATT_SMEM,
               (const __half*)q2, D_,
               (const __half*)kv, (const __half*)(kv + 512), 1024,
               EVL, 0, at);
    launch_pdl(gemm_hmma<0,0,0>, gP, dim3(256), GEMM_SMEM,
               (const __half*)at, (const __half*)(Wb + WO[7]),
               (const float*)nullptr, tmp, (__half*)nullptr, D_, D_);
    launch_pdl(addnorm_kernel<1>, gAN, dim3(128), 0,
               (const float*)Y, (const float*)tmp, G2, BE2, Z, x2);

    // ---- FFN ----
    launch_pdl(gemm_hmma<1,1,1>, gF1, dim3(256), GEMM_SMEM,
               (const __half*)x2, (const __half*)(Wb + WO[8]),
               b1, (float*)nullptr, Fb, F_, D_);
    launch_pdl(gemm_hmma<1,0,0>, gP, dim3(256), GEMM_SMEM,
               (const __half*)Fb, (const __half*)(Wb + WO[9]),
               b2, tmp, (__half*)nullptr, D_, F_);
    launch_pdl(addnorm_kernel<0>, gAN, dim3(128), 0,
               (const float*)Z, (const float*)tmp, G3, BE3, out,
               (__half*)nullptr);
}

// round 16
// speedup vs baseline: 2.4053x; 1.0089x over previous
#include <cuda_runtime.h>
#include <cuda_fp16.h>
#include <math.h>
#include <stdint.h>

// Problem constants
#define B_ 32
#define T_ 512
#define D_ 512
#define H_ 8
#define M_ (B_ * T_)   // 16384 rows
#define F_ 2048

// ---------------------------------------------------------------------------
// Scratch (device globals; no allocation allowed)
// ---------------------------------------------------------------------------
__device__ float g_tmp[(size_t)M_ * D_];
__device__ float g_Y  [(size_t)M_ * D_];
__device__ float g_Z  [(size_t)M_ * D_];

__device__ __half g_x1 [(size_t)M_ * D_];     // X / Y (fp16)
__device__ __half g_x2 [(size_t)M_ * D_];     // ENC / Z (fp16)
__device__ __half g_qkv[(size_t)M_ * 1536];   // self QKV fused
__device__ __half g_kv [(size_t)M_ * 1024];   // cross KV fused
__device__ __half g_q2 [(size_t)M_ * D_];     // cross Q
__device__ __half g_at [(size_t)M_ * D_];     // attention output
__device__ __half g_F  [(size_t)M_ * F_];     // FFN intermediate
__device__ __half g_W  [4194304];             // all weights fp16

// ---------------------------------------------------------------------------
// helpers
// ---------------------------------------------------------------------------
__device__ __forceinline__ uint32_t smem_u32(const void* p) {
    uint32_t a;
    asm("{ .reg .u64 t; cvta.to.shared.u64 t, %1; cvt.u32.u64 %0, t; }"
        : "=r"(a) : "l"(p));
    return a;
}

#define PDL_TRIGGER() asm volatile("griddepcontrol.launch_dependents;" ::: "memory")
#define PDL_WAIT()    asm volatile("griddepcontrol.wait;" ::: "memory")

#define CP_ASYNC16(dst, src) \
    asm volatile("cp.async.cg.shared.global [%0], [%1], 16;" :: \
                 "r"(dst), "l"(src) : "memory")
#define CP_COMMIT() asm volatile("cp.async.commit_group;" ::: "memory")
#define CP_WAIT(n)  asm volatile("cp.async.wait_group %0;" :: "n"(n) : "memory")

#define LDMATRIX_X4(r0, r1, r2, r3, addr) \
    asm volatile("ldmatrix.sync.aligned.m8n8.x4.shared.b16 {%0,%1,%2,%3}, [%4];" \
                 : "=r"(r0), "=r"(r1), "=r"(r2), "=r"(r3) : "r"(addr))

#define LDMATRIX_X4_T(r0, r1, r2, r3, addr) \
    asm volatile("ldmatrix.sync.aligned.m8n8.x4.trans.shared.b16 {%0,%1,%2,%3}, [%4];" \
                 : "=r"(r0), "=r"(r1), "=r"(r2), "=r"(r3) : "r"(addr))

#define MMA_F16(d0, d1, d2, d3, a0, a1, a2, a3, b0, b1) \
    asm volatile("mma.sync.aligned.m16n8k16.row.col.f32.f16.f16.f32 " \
                 "{%0,%1,%2,%3}, {%4,%5,%6,%7}, {%8,%9}, {%0,%1,%2,%3};" \
                 : "+f"(d0), "+f"(d1), "+f"(d2), "+f"(d3) \
                 : "r"(a0), "r"(a1), "r"(a2), "r"(a3), "r"(b0), "r"(b1))

__device__ __forceinline__ uint32_t packh2(float x, float y) {
    __half2 h = __floats2half2_rn(x, y);
    return *reinterpret_cast<uint32_t*>(&h);
}

// ---------------------------------------------------------------------------
// merged convert fp32 -> fp16: 12 segments in one launch
// ---------------------------------------------------------------------------
struct ConvSegs {
    const float* src[12];
    __half* dst[12];
    int n4[12];
};

__global__ void __launch_bounds__(256)
mconv_kernel(ConvSegs s)
{
    PDL_TRIGGER();
    int i = blockIdx.x * 256 + threadIdx.x;
#pragma unroll
    for (int k = 0; k < 12; k++) {
        if (i < s.n4[k]) {
            float4 v = ((const float4*)s.src[k])[i];
            uint32_t* dp = (uint32_t*)s.dst[k];
            dp[2 * i]     = packh2(v.x, v.y);
            dp[2 * i + 1] = packh2(v.z, v.w);
            return;
        }
        i -= s.n4[k];
    }
}

// ---------------------------------------------------------------------------
// fp16 HMMA GEMM: C[M,N] = A[M,K] @ W[N,K]^T (single pass, fp32 accum)
// 128x128 CTA tile, 128 threads, 4 warps (2 M x 2 N), warp tile 64x64.
// Per k-slice: 8 ldmatrix -> 32 independent MMAs (2x ILP of 64x32 tile,
// 128 B smem per MMA vs 192). K-chunk = 64 (two 32-col sub-tiles),
// XOR-swizzled 64B-row SMEM, 3-stage cp.async pipeline.
// ---------------------------------------------------------------------------
#define TILE_H 8192                  // 128 rows x 32 fp16 = 8 KB sub-tile
#define STAGE_B (4 * TILE_H)         // A0, A1, W0, W1 = 32768
#define GEMM_SMEM (3 * STAGE_B)      // 98304

template <int BIAS, int LEAKY, int CONV>
__device__ __forceinline__ void gemm_body(
    const __half* __restrict__ A, const __half* __restrict__ W,
    const float* __restrict__ bias, float* __restrict__ C,
    __half* __restrict__ Ch,
    int N, int K, int bm, int bn, char* smem)
{
    PDL_TRIGGER();
    const uint32_t sbase = smem_u32(smem);

    const int tid = threadIdx.x;
    const int wid = tid >> 5, lane = tid & 31;
    const int wm = wid & 1, wn = wid >> 1;     // 2 M x 2 N warp grid

    const int ldr0 = tid >> 2;            // row 0..31
    const int ldc4 = tid & 3;             // 16B-chunk 0..3
    const int ldce = ldc4 * 8;            // element col within sub-tile

    const __half* gA = A + (size_t)(bm + ldr0) * K + ldce;
    const __half* gW = W + (size_t)(bn + ldr0) * K + ldce;
    const size_t rstep = (size_t)32 * K;  // +32 rows

    uint32_t sro[4];
#pragma unroll
    for (int h = 0; h < 4; h++) {
        const int r = ldr0 + h * 32;
        sro[h] = (uint32_t)(r * 64 + ((ldc4 ^ ((r >> 1) & 3)) << 4));
    }

    const int aRowB = wm * 64 + (lane & 15);
    const int aKc0  = (lane >> 4);
    const int aSw   = (aRowB >> 1) & 3;
    const int bRowB = wn * 64 + (lane & 7) + ((lane >> 4) << 3);
    const int bKc0  = (lane >> 3) & 1;
    const int bSw   = (bRowB >> 1) & 3;

    float acc[4][8][4];
#pragma unroll
    for (int i = 0; i < 4; i++)
#pragma unroll
        for (int j = 0; j < 8; j++)
#pragma unroll
            for (int r = 0; r < 4; r++) acc[i][j][r] = 0.f;

    const int NC = K >> 6;   // chunks of 64

    auto load_chunk = [&](int c, int buf) {
        const uint32_t st = sbase + buf * STAGE_B;
        const int koff = c << 6;
#pragma unroll
        for (int h = 0; h < 4; h++) {
            CP_ASYNC16(st + sro[h],              gA + (size_t)h * rstep + koff);
            CP_ASYNC16(st + TILE_H + sro[h],     gA + (size_t)h * rstep + koff + 32);
            CP_ASYNC16(st + 2 * TILE_H + sro[h], gW + (size_t)h * rstep + koff);
            CP_ASYNC16(st + 3 * TILE_H + sro[h], gW + (size_t)h * rstep + koff + 32);
        }
        CP_COMMIT();
    };

    PDL_WAIT();
    load_chunk(0, 0);
    load_chunk(1, 1);
    int lbuf = 2, cbuf = 0;

    for (int c = 0; c < NC; c++) {
        if (c + 1 < NC) { CP_WAIT(1); } else { CP_WAIT(0); }
        __syncthreads();
        if (c + 2 < NC) {
            load_chunk(c + 2, lbuf);
            lbuf = (lbuf == 2) ? 0 : lbuf + 1;
        }

        const uint32_t st = sbase + cbuf * STAGE_B;
        cbuf = (cbuf == 2) ? 0 : cbuf + 1;

#pragma unroll
        for (int sub = 0; sub < 2; sub++) {
            const uint32_t aB = st + sub * TILE_H;
            const uint32_t bB = st + (2 + sub) * TILE_H;
#pragma unroll
            for (int ks = 0; ks < 2; ks++) {
                const uint32_t aoff = (uint32_t)(aRowB * 64 +
                                      (((ks * 2 + aKc0) ^ aSw) << 4));
                const uint32_t boff = (uint32_t)(bRowB * 64 +
                                      (((ks * 2 + bKc0) ^ bSw) << 4));

                // B frags: 8 n8 frags (4 ldmatrix.x4)
                uint32_t b[8][2];
#pragma unroll
                for (int j2 = 0; j2 < 4; j2++) {
                    uint32_t r0, r1, r2, r3;
                    LDMATRIX_X4(r0, r1, r2, r3, bB + boff + j2 * 1024);
                    b[j2 * 2 + 0][0] = r0; b[j2 * 2 + 0][1] = r1;
                    b[j2 * 2 + 1][0] = r2; b[j2 * 2 + 1][1] = r3;
                }
                uint32_t a[4][4];
#pragma unroll
                for (int i = 0; i < 4; i++)
                    LDMATRIX_X4(a[i][0], a[i][1], a[i][2], a[i][3],
                                aB + aoff + i * 1024);
#pragma unroll
                for (int i = 0; i < 4; i++)
#pragma unroll
                    for (int j = 0; j < 8; j++)
                        MMA_F16(acc[i][j][0], acc[i][j][1], acc[i][j][2], acc[i][j][3],
                                a[i][0], a[i][1], a[i][2], a[i][3], b[j][0], b[j][1]);
            }
        }
    }

    const int tg = lane >> 2;
    const int tc = (lane & 3) * 2;
#pragma unroll
    for (int i = 0; i < 4; i++) {
        const int r0 = bm + wm * 64 + i * 16 + tg;
#pragma unroll
        for (int j = 0; j < 8; j++) {
            const int col = bn + wn * 64 + j * 8 + tc;
            float v0 = acc[i][j][0], v1 = acc[i][j][1];
            float v2 = acc[i][j][2], v3 = acc[i][j][3];
            if (BIAS) {
                const float b0 = bias[col], b1 = bias[col + 1];
                v0 += b0; v1 += b1; v2 += b0; v3 += b1;
            }
            if (LEAKY) {
                v0 = v0 > 0.f ? v0 : 0.01f * v0;
                v1 = v1 > 0.f ? v1 : 0.01f * v1;
                v2 = v2 > 0.f ? v2 : 0.01f * v2;
                v3 = v3 > 0.f ? v3 : 0.01f * v3;
            }
            if (CONV) {
                *(uint32_t*)&Ch[(size_t)r0 * N + col]       = packh2(v0, v1);
                *(uint32_t*)&Ch[(size_t)(r0 + 8) * N + col] = packh2(v2, v3);
            } else {
                *(float2*)&C[(size_t)r0 * N + col]       = make_float2(v0, v1);
                *(float2*)&C[(size_t)(r0 + 8) * N + col] = make_float2(v2, v3);
            }
        }
    }
}

template <int BIAS, int LEAKY, int CONV>
__global__ void __launch_bounds__(128, 2)
gemm_hmma(const __half* __restrict__ A, const __half* __restrict__ W,
          const float* __restrict__ bias, float* __restrict__ C,
          __half* __restrict__ Ch, int N, int K)
{
    extern __shared__ __align__(16) char smem[];
    gemm_body<BIAS, LEAKY, CONV>(A, W, bias, C, Ch,
                                 N, K, blockIdx.y * 128, blockIdx.x * 128, smem);
}

// Two independent fp16-out GEMM jobs in one launch (cross-attn Q2 + KV)
__global__ void __launch_bounds__(128, 2)
gemm_dual(const __half* A0, const __half* W0, __half* C0, int N0, int nb0,
          const __half* A1, const __half* W1, __half* C1, int N1, int K)
{
    extern __shared__ __align__(16) char smem[];
    if ((int)blockIdx.x < nb0)
        gemm_body<0, 0, 1>(A0, W0, nullptr, nullptr, C0,
                           N0, K, blockIdx.y * 128, blockIdx.x * 128, smem);
    else
        gemm_body<0, 0, 1>(A1, W1, nullptr, nullptr, C1,
                           N1, K, blockIdx.y * 128, (blockIdx.x - nb0) * 128, smem);
}

// ---------------------------------------------------------------------------
// fp16 HMMA flash attention (single pass), cp.async 2-stage K/V pipeline.
// ---------------------------------------------------------------------------
#define AROWB 144
#define KV_STAGE 18432                       // K (64x144) + V (64x144)
#define ATT_SMEM (18432 + 2 * KV_STAGE)      // Q + 2 stages = 55296

__global__ void __launch_bounds__(256, 2)
attn_hmma(const __half* __restrict__ Q, int qs,
          const __half* __restrict__ K, const __half* __restrict__ V, int kvs,
          const int* __restrict__ vlp, int per_row,
          __half* __restrict__ O)
{
    PDL_TRIGGER();
    extern __shared__ __align__(16) char sm[];
    char* cQ = sm;
    const uint32_t uQ  = smem_u32(cQ);
    const uint32_t uKV = smem_u32(sm + 18432);
    __shared__ int sred[8];

    const int tid = threadIdx.x;
    const int w = tid >> 5, lane = tid & 31;
    const int g = lane >> 2, c = lane & 3;
    const int b = blockIdx.x >> 3, h = blockIdx.x & 7;
    const int q0 = blockIdx.y * 128;

    int kmax;
    if (per_row) {
        int v = (tid < 128) ? vlp[b * T_ + q0 + tid] : 0;
#pragma unroll
        for (int off = 16; off; off >>= 1)
            v = max(v, __shfl_xor_sync(0xffffffffu, v, off));
        if (lane == 0) sred[w] = v;
        __syncthreads();
        kmax = sred[0];
#pragma unroll
        for (int i = 1; i < 8; i++) kmax = max(kmax, sred[i]);
    } else {
        kmax = vlp[b];
    }
    const int nkt = (kmax + 63) >> 6;

    int vl0, vl1;
    if (per_row) {
        vl0 = vlp[b * T_ + q0 + w * 16 + g];
        vl1 = vlp[b * T_ + q0 + w * 16 + g + 8];
    } else {
        vl0 = vl1 = kmax;
    }

    PDL_WAIT();

    const __half* qp = Q + (size_t)(b * T_ + q0) * qs + h * 64;
    for (int i = tid; i < 1024; i += 256) {
        const int r = i >> 3, ch = i & 7;
        *(uint4*)(cQ + r * AROWB + ch * 16) =
            *(const uint4*)(qp + (size_t)r * qs + ch * 8);
    }

    auto load_kv = [&](int kt, int stg) {
        const size_t kb = (size_t)(b * T_ + kt * 64) * kvs + h * 64;
        const uint32_t sb = uKV + stg * KV_STAGE;
        for (int i = tid; i < 512; i += 256) {
            const int r = i >> 3, ch = i & 7;
            const size_t go = kb + (size_t)r * kvs + ch * 8;
            const uint32_t so = r * AROWB + ch * 16;
            CP_ASYNC16(sb + so,        K + go);
            CP_ASYNC16(sb + 9216 + so, V + go);
        }
        CP_COMMIT();
    };
    load_kv(0, 0);

    float m0 = -1e30f, m1 = -1e30f, l0 = 0.f, l1 = 0.f;
    float o[8][4];
#pragma unroll
    for (int j = 0; j < 8; j++)
#pragma unroll
        for (int e = 0; e < 4; e++) o[j][e] = 0.f;

    const uint32_t qaddr = (w * 16 + (lane & 15)) * AROWB + (lane >> 4) * 16;
    const int bRow = (lane & 7) + ((lane >> 4) << 3);
    const int bK8  = ((lane >> 3) & 1) * 16;
    const int vRow = (lane & 7) + ((lane >> 3) & 1) * 8;
    const int vColB = (lane >> 4) * 16;

    for (int kt = 0; kt < nkt; kt++) {
        __syncthreads();
        if (kt + 1 < nkt) {
            load_kv(kt + 1, (kt + 1) & 1);
            CP_WAIT(1);
        } else {
            CP_WAIT(0);
        }
        __syncthreads();

        const uint32_t sK = uKV + (kt & 1) * KV_STAGE;
        const uint32_t uK = sK, uV = sK + 9216;

        float s[8][4];
#pragma unroll
        for (int j = 0; j < 8; j++)
#pragma unroll
            for (int e = 0; e < 4; e++) s[j][e] = 0.f;

#pragma unroll
        for (int kk = 0; kk < 4; kk++) {
            uint32_t a0, a1, a2, a3;
            LDMATRIX_X4(a0, a1, a2, a3, uQ + qaddr + kk * 32);
#pragma unroll
            for (int j2 = 0; j2 < 4; j2++) {
                uint32_t r0, r1, r2, r3;
                LDMATRIX_X4(r0, r1, r2, r3,
                            uK + (j2 * 16 + bRow) * AROWB + kk * 32 + bK8);
                MMA_F16(s[2*j2][0], s[2*j2][1], s[2*j2][2], s[2*j2][3],
                        a0, a1, a2, a3, r0, r1);
                MMA_F16(s[2*j2+1][0], s[2*j2+1][1], s[2*j2+1][2], s[2*j2+1][3],
                        a0, a1, a2, a3, r2, r3);
            }
        }

        const int kof = kt * 64 + c * 2;
        float mx0 = -1e30f, mx1 = -1e30f;
#pragma unroll
        for (int j = 0; j < 8; j++) {
            const int ki = kof + j * 8;
            s[j][0] = (ki     < vl0) ? s[j][0] * 0.125f : -1e10f;
            s[j][1] = (ki + 1 < vl0) ? s[j][1] * 0.125f : -1e10f;
            s[j][2] = (ki     < vl1) ? s[j][2] * 0.125f : -1e10f;
            s[j][3] = (ki + 1 < vl1) ? s[j][3] * 0.125f : -1e10f;
            mx0 = fmaxf(mx0, fmaxf(s[j][0], s[j][1]));
            mx1 = fmaxf(mx1, fmaxf(s[j][2], s[j][3]));
        }
        mx0 = fmaxf(mx0, __shfl_xor_sync(0xffffffffu, mx0, 1));
        mx0 = fmaxf(mx0, __shfl_xor_sync(0xffffffffu, mx0, 2));
        mx1 = fmaxf(mx1, __shfl_xor_sync(0xffffffffu, mx1, 1));
        mx1 = fmaxf(mx1, __shfl_xor_sync(0xffffffffu, mx1, 2));

        const float mn0 = fmaxf(m0, mx0), mn1 = fmaxf(m1, mx1);
        const float al_0 = __expf(m0 - mn0), al_1 = __expf(m1 - mn1);
        m0 = mn0; m1 = mn1;

        float rs0 = 0.f, rs1 = 0.f;
#pragma unroll
        for (int j = 0; j < 8; j++) {
            s[j][0] = __expf(s[j][0] - mn0);
            s[j][1] = __expf(s[j][1] - mn0);
            s[j][2] = __expf(s[j][2] - mn1);
            s[j][3] = __expf(s[j][3] - mn1);
            rs0 += s[j][0] + s[j][1];
            rs1 += s[j][2] + s[j][3];
        }
        rs0 += __shfl_xor_sync(0xffffffffu, rs0, 1);
        rs0 += __shfl_xor_sync(0xffffffffu, rs0, 2);
        rs1 += __shfl_xor_sync(0xffffffffu, rs1, 1);
        rs1 += __shfl_xor_sync(0xffffffffu, rs1, 2);
        l0 = l0 * al_0 + rs0;
        l1 = l1 * al_1 + rs1;

#pragma unroll
        for (int j = 0; j < 8; j++) {
            o[j][0] *= al_0; o[j][1] *= al_0;
            o[j][2] *= al_1; o[j][3] *= al_1;
        }

#pragma unroll
        for (int t = 0; t < 4; t++) {
            uint32_t p[4];
            p[0] = packh2(s[2*t][0],   s[2*t][1]);
            p[1] = packh2(s[2*t][2],   s[2*t][3]);
            p[2] = packh2(s[2*t+1][0], s[2*t+1][1]);
            p[3] = packh2(s[2*t+1][2], s[2*t+1][3]);
#pragma unroll
            for (int j2 = 0; j2 < 4; j2++) {
                uint32_t r0, r1, r2, r3;
                LDMATRIX_X4_T(r0, r1, r2, r3,
                              uV + (t * 16 + vRow) * AROWB + j2 * 32 + vColB);
                MMA_F16(o[2*j2][0], o[2*j2][1], o[2*j2][2], o[2*j2][3],
                        p[0], p[1], p[2], p[3], r0, r1);
                MMA_F16(o[2*j2+1][0], o[2*j2+1][1], o[2*j2+1][2], o[2*j2+1][3],
                        p[0], p[1], p[2], p[3], r2, r3);
            }
        }
    }

    const float il0 = 1.0f / l0, il1 = 1.0f / l1;
    const int r0g = b * T_ + q0 + w * 16 + g;
    const int r1g = r0g + 8;
#pragma unroll
    for (int j = 0; j < 8; j++) {
        const int col = h * 64 + j * 8 + c * 2;
        *(uint32_t*)&O[(size_t)r0g * D_ + col] = packh2(o[j][0] * il0, o[j][1] * il0);
        *(uint32_t*)&O[(size_t)r1g * D_ + col] = packh2(o[j][2] * il1, o[j][3] * il1);
    }
}

// ---------------------------------------------------------------------------
// out = LayerNorm(A + Bt) * g + be ; CONV=1 also emits fp16
// ---------------------------------------------------------------------------
template <int CONV>
__global__ void __launch_bounds__(128)
addnorm_kernel(const float* __restrict__ A, const float* __restrict__ Bt,
               const float* __restrict__ g, const float* __restrict__ be,
               float* __restrict__ out, __half* __restrict__ oh)
{
    PDL_TRIGGER();
    PDL_WAIT();
    const int row = blockIdx.x;
    const int tid = threadIdx.x;
    const size_t base = (size_t)row * D_;

    float4 a = *(const float4*)&A[base + tid * 4];
    float4 b = *(const float4*)&Bt[base + tid * 4];
    float4 x = make_float4(a.x + b.x, a.y + b.y, a.z + b.z, a.w + b.w);

    float s  = x.x + x.y + x.z + x.w;
    float sq = x.x * x.x + x.y * x.y + x.z * x.z + x.w * x.w;
#pragma unroll
    for (int off = 16; off; off >>= 1) {
        s  += __shfl_xor_sync(0xffffffffu, s,  off);
        sq += __shfl_xor_sync(0xffffffffu, sq, off);
    }
    __shared__ float ss[4], ssq[4];
    if ((tid & 31) == 0) { ss[tid >> 5] = s; ssq[tid >> 5] = sq; }
    __syncthreads();
    s  = ss[0] + ss[1] + ss[2] + ss[3];
    sq = ssq[0] + ssq[1] + ssq[2] + ssq[3];

    float mu  = s * (1.0f / D_);
    float var = sq * (1.0f / D_) - mu * mu;
    float inv = rsqrtf(var + 1e-5f);

    float4 gg = *(const float4*)&g[tid * 4];
    float4 bb = *(const float4*)&be[tid * 4];
    float4 oo = make_float4((x.x - mu) * inv * gg.x + bb.x,
                            (x.y - mu) * inv * gg.y + bb.y,
                            (x.z - mu) * inv * gg.z + bb.z,
                            (x.w - mu) * inv * gg.w + bb.w);
    *(float4*)&out[base + tid * 4] = oo;
    if (CONV) {
        uint32_t* hp = (uint32_t*)&oh[base + tid * 4];
        hp[0] = packh2(oo.x, oo.y);
        hp[1] = packh2(oo.z, oo.w);
    }
}

// ---------------------------------------------------------------------------
// PDL launch helper
// ---------------------------------------------------------------------------
template <typename... ExpT, typename... ActT>
static void launch_pdl(void (*kern)(ExpT...), dim3 gr, dim3 bl, size_t shm,
                       ActT... args)
{
    cudaLaunchConfig_t cfg = {};
    cfg.gridDim = gr;
    cfg.blockDim = bl;
    cfg.dynamicSmemBytes = shm;
    cfg.stream = 0;
    cudaLaunchAttribute at[1];
    at[0].id = cudaLaunchAttributeProgrammaticStreamSerialization;
    at[0].val.programmaticStreamSerializationAllowed = 1;
    cfg.attrs = at;
    cfg.numAttrs = 1;
    cudaLaunchKernelEx(&cfg, kern, args...);
}

// ---------------------------------------------------------------------------
// Launch
// ---------------------------------------------------------------------------
extern "C" void kernel_launch(void* const* d_in, const int* in_sizes, int n_in,
                              void* d_out, int out_size)
{
    const float* X    = (const float*)d_in[0];
    const float* ENC  = (const float*)d_in[1];
    const int*   DVL  = (const int*)d_in[2];
    const int*   EVL  = (const int*)d_in[3];
    const float* Wmat[8] = {
        (const float*)d_in[4],  (const float*)d_in[5],
        (const float*)d_in[6],  (const float*)d_in[7],
        (const float*)d_in[8],  (const float*)d_in[9],
        (const float*)d_in[10], (const float*)d_in[11]};
    const float* W1   = (const float*)d_in[12];
    const float* b1   = (const float*)d_in[13];
    const float* W2   = (const float*)d_in[14];
    const float* b2   = (const float*)d_in[15];
    const float* G1   = (const float*)d_in[16];
    const float* BE1  = (const float*)d_in[17];
    const float* G2   = (const float*)d_in[18];
    const float* BE2  = (const float*)d_in[19];
    const float* G3   = (const float*)d_in[20];
    const float* BE3  = (const float*)d_in[21];
    float* out = (float*)d_out;

    float *tmp, *Y, *Z;
    __half *x1, *x2, *qkv, *kv, *q2, *at, *Fb, *Wb;
    cudaGetSymbolAddress((void**)&tmp, g_tmp);
    cudaGetSymbolAddress((void**)&Y,   g_Y);
    cudaGetSymbolAddress((void**)&Z,   g_Z);
    cudaGetSymbolAddress((void**)&x1,  g_x1);
    cudaGetSymbolAddress((void**)&x2,  g_x2);
    cudaGetSymbolAddress((void**)&qkv, g_qkv);
    cudaGetSymbolAddress((void**)&kv,  g_kv);
    cudaGetSymbolAddress((void**)&q2,  g_q2);
    cudaGetSymbolAddress((void**)&at,  g_at);
    cudaGetSymbolAddress((void**)&Fb,  g_F);
    cudaGetSymbolAddress((void**)&Wb,  g_W);

    cudaFuncSetAttribute(attn_hmma,
                         cudaFuncAttributeMaxDynamicSharedMemorySize, ATT_SMEM);
    cudaFuncSetAttribute(gemm_hmma<0, 0, 1>,
                         cudaFuncAttributeMaxDynamicSharedMemorySize, GEMM_SMEM);
    cudaFuncSetAttribute(gemm_hmma<0, 0, 0>,
                         cudaFuncAttributeMaxDynamicSharedMemorySize, GEMM_SMEM);
    cudaFuncSetAttribute(gemm_hmma<1, 1, 1>,
                         cudaFuncAttributeMaxDynamicSharedMemorySize, GEMM_SMEM);
    cudaFuncSetAttribute(gemm_hmma<1, 0, 0>,
                         cudaFuncAttributeMaxDynamicSharedMemorySize, GEMM_SMEM);
    cudaFuncSetAttribute(gemm_dual,
                         cudaFuncAttributeMaxDynamicSharedMemorySize, GEMM_SMEM);

    size_t WO[10];
    for (int i = 0; i < 8; i++) WO[i] = (size_t)i * D_ * D_;
    WO[8] = 8ull * D_ * D_;
    WO[9] = WO[8] + (size_t)F_ * D_;

    const int nDD = D_ * D_ / 4;       // 65536
    const int nMD = M_ * D_ / 4;       // 2097152
    const int nFD = F_ * D_ / 4;       // 262144

    ConvSegs segs;
    int total4 = 0;
    for (int i = 0; i < 8; i++) {
        segs.src[i] = Wmat[i];
        segs.dst[i] = Wb + WO[i];
        segs.n4[i] = nDD; total4 += nDD;
    }
    segs.src[8] = W1; segs.dst[8] = Wb + WO[8]; segs.n4[8] = nFD; total4 += nFD;
    segs.src[9] = W2; segs.dst[9] = Wb + WO[9]; segs.n4[9] = nFD; total4 += nFD;
    segs.src[10] = X;   segs.dst[10] = x1; segs.n4[10] = nMD; total4 += nMD;
    segs.src[11] = ENC; segs.dst[11] = x2; segs.n4[11] = nMD; total4 += nMD;
    launch_pdl(mconv_kernel, dim3((total4 + 255) / 256), dim3(256), 0, segs);

    dim3 gQKV(1536 / 128, M_ / 128);   // (12, 128)
    dim3 gDUO(12,         M_ / 128);   // q2(4) + kv(8)
    dim3 gP  (D_ / 128,   M_ / 128);   // (4, 128)
    dim3 gF1 (F_ / 128,   M_ / 128);   // (16, 128)
    dim3 gA  (B_ * H_,    T_ / 128);   // (256, 4)
    dim3 gAN (M_);

    // ---- self-attention ----
    launch_pdl(gemm_hmma<0,0,1>, gQKV, dim3(128), GEMM_SMEM,
               (const __half*)x1, (const __half*)(Wb + WO[0]),
               (const float*)nullptr, (float*)nullptr, qkv, 1536, D_);
    launch_pdl(attn_hmma, gA, dim3(256), (size_t)ATT_SMEM,
               (const __half*)qkv, 1536,
               (const __half*)(qkv + 512), (const __half*)(qkv + 1024), 1536,
               DVL, 1, at);
    launch_pdl(gemm_hmma<0,0,0>, gP, dim3(128), GEMM_SMEM,
               (const __half*)at, (const __half*)(Wb + WO[3]),
               (const float*)nullptr, tmp, (__half*)nullptr, D_, D_);
    launch_pdl(addnorm_kernel<1>, gAN, dim3(128), 0,
               X, (const float*)tmp, G1, BE1, Y, x1);

    // ---- cross-attention (Q2 + KV in one launch) ----
    launch_pdl(gemm_dual, gDUO, dim3(128), GEMM_SMEM,
               (const __half*)x1, (const __half*)(Wb + WO[4]), q2, 512, 4,
               (const __half*)x2, (const __half*)(Wb + WO[5]), kv, 1024, D_);
    launch_pdl(attn_hmma, gA, dim3(256), (size_t)ATT_SMEM,
               (const __half*)q2, D_,
               (const __half*)kv, (const __half*)(kv + 512), 1024,
               EVL, 0, at);
    launch_pdl(gemm_hmma<0,0,0>, gP, dim3(128), GEMM_SMEM,
               (const __half*)at, (const __half*)(Wb + WO[7]),
               (const float*)nullptr, tmp, (__half*)nullptr, D_, D_);
    launch_pdl(addnorm_kernel<1>, gAN, dim3(128), 0,
               (const float*)Y, (const float*)tmp, G2, BE2, Z, x2);

    // ---- FFN ----
    launch_pdl(gemm_hmma<1,1,1>, gF1, dim3(128), GEMM_SMEM,
               (const __half*)x2, (const __half*)(Wb + WO[8]),
               b1, (float*)nullptr, Fb, F_, D_);
    launch_pdl(gemm_hmma<1,0,0>, gP, dim3(128), GEMM_SMEM,
               (const __half*)Fb, (const __half*)(Wb + WO[9]),
               b2, tmp, (__half*)nullptr, D_, F_);
    launch_pdl(addnorm_kernel<0>, gAN, dim3(128), 0,
               (const float*)Z, (const float*)tmp, G3, BE3, out,
               (__half*)nullptr);
}

// round 17
// speedup vs baseline: 2.4094x; 1.0017x over previous
#include <cuda_runtime.h>
#include <cuda_fp16.h>
#include <math.h>
#include <stdint.h>

// Problem constants
#define B_ 32
#define T_ 512
#define D_ 512
#define H_ 8
#define M_ (B_ * T_)   // 16384 rows
#define F_ 2048

// ---------------------------------------------------------------------------
// Scratch (device globals; no allocation allowed)
// ---------------------------------------------------------------------------
__device__ float g_Y  [(size_t)M_ * D_];
__device__ float g_Z  [(size_t)M_ * D_];

__device__ __half g_tmph[(size_t)M_ * D_];    // GEMM outputs feeding addnorm
__device__ __half g_x1 [(size_t)M_ * D_];     // X / Y (fp16)
__device__ __half g_x2 [(size_t)M_ * D_];     // ENC / Z (fp16)
__device__ __half g_qkv[(size_t)M_ * 1536];   // self QKV fused
__device__ __half g_kv [(size_t)M_ * 1024];   // cross KV fused
__device__ __half g_q2 [(size_t)M_ * D_];     // cross Q
__device__ __half g_at [(size_t)M_ * D_];     // attention output
__device__ __half g_F  [(size_t)M_ * F_];     // FFN intermediate
__device__ __half g_W  [4194304];             // all weights fp16

// ---------------------------------------------------------------------------
// helpers
// ---------------------------------------------------------------------------
__device__ __forceinline__ uint32_t smem_u32(const void* p) {
    uint32_t a;
    asm("{ .reg .u64 t; cvta.to.shared.u64 t, %1; cvt.u32.u64 %0, t; }"
        : "=r"(a) : "l"(p));
    return a;
}

#define PDL_TRIGGER() asm volatile("griddepcontrol.launch_dependents;" ::: "memory")
#define PDL_WAIT()    asm volatile("griddepcontrol.wait;" ::: "memory")

#define CP_ASYNC16(dst, src) \
    asm volatile("cp.async.cg.shared.global [%0], [%1], 16;" :: \
                 "r"(dst), "l"(src) : "memory")
#define CP_COMMIT() asm volatile("cp.async.commit_group;" ::: "memory")
#define CP_WAIT(n)  asm volatile("cp.async.wait_group %0;" :: "n"(n) : "memory")

#define LDMATRIX_X4(r0, r1, r2, r3, addr) \
    asm volatile("ldmatrix.sync.aligned.m8n8.x4.shared.b16 {%0,%1,%2,%3}, [%4];" \
                 : "=r"(r0), "=r"(r1), "=r"(r2), "=r"(r3) : "r"(addr))

#define LDMATRIX_X4_T(r0, r1, r2, r3, addr) \
    asm volatile("ldmatrix.sync.aligned.m8n8.x4.trans.shared.b16 {%0,%1,%2,%3}, [%4];" \
                 : "=r"(r0), "=r"(r1), "=r"(r2), "=r"(r3) : "r"(addr))

#define MMA_F16(d0, d1, d2, d3, a0, a1, a2, a3, b0, b1) \
    asm volatile("mma.sync.aligned.m16n8k16.row.col.f32.f16.f16.f32 " \
                 "{%0,%1,%2,%3}, {%4,%5,%6,%7}, {%8,%9}, {%0,%1,%2,%3};" \
                 : "+f"(d0), "+f"(d1), "+f"(d2), "+f"(d3) \
                 : "r"(a0), "r"(a1), "r"(a2), "r"(a3), "r"(b0), "r"(b1))

__device__ __forceinline__ uint32_t packh2(float x, float y) {
    __half2 h = __floats2half2_rn(x, y);
    return *reinterpret_cast<uint32_t*>(&h);
}

// ---------------------------------------------------------------------------
// merged convert fp32 -> fp16: 12 segments in one launch
// ---------------------------------------------------------------------------
struct ConvSegs {
    const float* src[12];
    __half* dst[12];
    int n4[12];
};

__global__ void __launch_bounds__(256)
mconv_kernel(ConvSegs s)
{
    PDL_TRIGGER();
    int i = blockIdx.x * 256 + threadIdx.x;
#pragma unroll
    for (int k = 0; k < 12; k++) {
        if (i < s.n4[k]) {
            float4 v = ((const float4*)s.src[k])[i];
            uint32_t* dp = (uint32_t*)s.dst[k];
            dp[2 * i]     = packh2(v.x, v.y);
            dp[2 * i + 1] = packh2(v.z, v.w);
            return;
        }
        i -= s.n4[k];
    }
}

// ---------------------------------------------------------------------------
// fp16 HMMA GEMM: C[M,N] = A[M,K] @ W[N,K]^T (single pass, fp32 accum)
// 128x128 CTA tile, 128 threads, 4 warps (2 M x 2 N), warp tile 64x64.
// K-chunk = 64, XOR-swizzled 64B-row SMEM, 3-stage cp.async pipeline.
// Output always fp16 (CONV path); fp32 output no longer needed anywhere.
// ---------------------------------------------------------------------------
#define TILE_H 8192                  // 128 rows x 32 fp16 = 8 KB sub-tile
#define STAGE_B (4 * TILE_H)         // A0, A1, W0, W1 = 32768
#define GEMM_SMEM (3 * STAGE_B)      // 98304

template <int BIAS, int LEAKY>
__device__ __forceinline__ void gemm_body(
    const __half* __restrict__ A, const __half* __restrict__ W,
    const float* __restrict__ bias, __half* __restrict__ Ch,
    int N, int K, int bm, int bn, char* smem)
{
    PDL_TRIGGER();
    const uint32_t sbase = smem_u32(smem);

    const int tid = threadIdx.x;
    const int wid = tid >> 5, lane = tid & 31;
    const int wm = wid & 1, wn = wid >> 1;     // 2 M x 2 N warp grid

    const int ldr0 = tid >> 2;            // row 0..31
    const int ldc4 = tid & 3;             // 16B-chunk 0..3
    const int ldce = ldc4 * 8;            // element col within sub-tile

    const __half* gA = A + (size_t)(bm + ldr0) * K + ldce;
    const __half* gW = W + (size_t)(bn + ldr0) * K + ldce;
    const size_t rstep = (size_t)32 * K;  // +32 rows

    uint32_t sro[4];
#pragma unroll
    for (int h = 0; h < 4; h++) {
        const int r = ldr0 + h * 32;
        sro[h] = (uint32_t)(r * 64 + ((ldc4 ^ ((r >> 1) & 3)) << 4));
    }

    const int aRowB = wm * 64 + (lane & 15);
    const int aKc0  = (lane >> 4);
    const int aSw   = (aRowB >> 1) & 3;
    const int bRowB = wn * 64 + (lane & 7) + ((lane >> 4) << 3);
    const int bKc0  = (lane >> 3) & 1;
    const int bSw   = (bRowB >> 1) & 3;

    float acc[4][8][4];
#pragma unroll
    for (int i = 0; i < 4; i++)
#pragma unroll
        for (int j = 0; j < 8; j++)
#pragma unroll
            for (int r = 0; r < 4; r++) acc[i][j][r] = 0.f;

    const int NC = K >> 6;   // chunks of 64

    auto load_chunk = [&](int c, int buf) {
        const uint32_t st = sbase + buf * STAGE_B;
        const int koff = c << 6;
#pragma unroll
        for (int h = 0; h < 4; h++) {
            CP_ASYNC16(st + sro[h],              gA + (size_t)h * rstep + koff);
            CP_ASYNC16(st + TILE_H + sro[h],     gA + (size_t)h * rstep + koff + 32);
            CP_ASYNC16(st + 2 * TILE_H + sro[h], gW + (size_t)h * rstep + koff);
            CP_ASYNC16(st + 3 * TILE_H + sro[h], gW + (size_t)h * rstep + koff + 32);
        }
        CP_COMMIT();
    };

    PDL_WAIT();
    load_chunk(0, 0);
    load_chunk(1, 1);
    int lbuf = 2, cbuf = 0;

    for (int c = 0; c < NC; c++) {
        if (c + 1 < NC) { CP_WAIT(1); } else { CP_WAIT(0); }
        __syncthreads();
        if (c + 2 < NC) {
            load_chunk(c + 2, lbuf);
            lbuf = (lbuf == 2) ? 0 : lbuf + 1;
        }

        const uint32_t st = sbase + cbuf * STAGE_B;
        cbuf = (cbuf == 2) ? 0 : cbuf + 1;

#pragma unroll
        for (int sub = 0; sub < 2; sub++) {
            const uint32_t aB = st + sub * TILE_H;
            const uint32_t bB = st + (2 + sub) * TILE_H;
#pragma unroll
            for (int ks = 0; ks < 2; ks++) {
                const uint32_t aoff = (uint32_t)(aRowB * 64 +
                                      (((ks * 2 + aKc0) ^ aSw) << 4));
                const uint32_t boff = (uint32_t)(bRowB * 64 +
                                      (((ks * 2 + bKc0) ^ bSw) << 4));

                uint32_t b[8][2];
#pragma unroll
                for (int j2 = 0; j2 < 4; j2++) {
                    uint32_t r0, r1, r2, r3;
                    LDMATRIX_X4(r0, r1, r2, r3, bB + boff + j2 * 1024);
                    b[j2 * 2 + 0][0] = r0; b[j2 * 2 + 0][1] = r1;
                    b[j2 * 2 + 1][0] = r2; b[j2 * 2 + 1][1] = r3;
                }
                uint32_t a[4][4];
#pragma unroll
                for (int i = 0; i < 4; i++)
                    LDMATRIX_X4(a[i][0], a[i][1], a[i][2], a[i][3],
                                aB + aoff + i * 1024);
#pragma unroll
                for (int i = 0; i < 4; i++)
#pragma unroll
                    for (int j = 0; j < 8; j++)
                        MMA_F16(acc[i][j][0], acc[i][j][1], acc[i][j][2], acc[i][j][3],
                                a[i][0], a[i][1], a[i][2], a[i][3], b[j][0], b[j][1]);
            }
        }
    }

    const int tg = lane >> 2;
    const int tc = (lane & 3) * 2;
#pragma unroll
    for (int i = 0; i < 4; i++) {
        const int r0 = bm + wm * 64 + i * 16 + tg;
#pragma unroll
        for (int j = 0; j < 8; j++) {
            const int col = bn + wn * 64 + j * 8 + tc;
            float v0 = acc[i][j][0], v1 = acc[i][j][1];
            float v2 = acc[i][j][2], v3 = acc[i][j][3];
            if (BIAS) {
                const float b0 = bias[col], b1 = bias[col + 1];
                v0 += b0; v1 += b1; v2 += b0; v3 += b1;
            }
            if (LEAKY) {
                v0 = v0 > 0.f ? v0 : 0.01f * v0;
                v1 = v1 > 0.f ? v1 : 0.01f * v1;
                v2 = v2 > 0.f ? v2 : 0.01f * v2;
                v3 = v3 > 0.f ? v3 : 0.01f * v3;
            }
            *(uint32_t*)&Ch[(size_t)r0 * N + col]       = packh2(v0, v1);
            *(uint32_t*)&Ch[(size_t)(r0 + 8) * N + col] = packh2(v2, v3);
        }
    }
}

template <int BIAS, int LEAKY>
__global__ void __launch_bounds__(128, 2)
gemm_hmma(const __half* __restrict__ A, const __half* __restrict__ W,
          const float* __restrict__ bias, __half* __restrict__ Ch, int N, int K)
{
    extern __shared__ __align__(16) char smem[];
    gemm_body<BIAS, LEAKY>(A, W, bias, Ch,
                           N, K, blockIdx.y * 128, blockIdx.x * 128, smem);
}

// Two independent fp16-out GEMM jobs in one launch (cross-attn Q2 + KV)
__global__ void __launch_bounds__(128, 2)
gemm_dual(const __half* A0, const __half* W0, __half* C0, int N0, int nb0,
          const __half* A1, const __half* W1, __half* C1, int N1, int K)
{
    extern __shared__ __align__(16) char smem[];
    if ((int)blockIdx.x < nb0)
        gemm_body<0, 0>(A0, W0, nullptr, C0,
                        N0, K, blockIdx.y * 128, blockIdx.x * 128, smem);
    else
        gemm_body<0, 0>(A1, W1, nullptr, C1,
                        N1, K, blockIdx.y * 128, (blockIdx.x - nb0) * 128, smem);
}

// ---------------------------------------------------------------------------
// fp16 HMMA flash attention (single pass), cp.async 2-stage K/V pipeline.
// ---------------------------------------------------------------------------
#define AROWB 144
#define KV_STAGE 18432                       // K (64x144) + V (64x144)
#define ATT_SMEM (18432 + 2 * KV_STAGE)      // Q + 2 stages = 55296

__global__ void __launch_bounds__(256, 2)
attn_hmma(const __half* __restrict__ Q, int qs,
          const __half* __restrict__ K, const __half* __restrict__ V, int kvs,
          const int* __restrict__ vlp, int per_row,
          __half* __restrict__ O)
{
    PDL_TRIGGER();
    extern __shared__ __align__(16) char sm[];
    char* cQ = sm;
    const uint32_t uQ  = smem_u32(cQ);
    const uint32_t uKV = smem_u32(sm + 18432);
    __shared__ int sred[8];

    const int tid = threadIdx.x;
    const int w = tid >> 5, lane = tid & 31;
    const int g = lane >> 2, c = lane & 3;
    const int b = blockIdx.x >> 3, h = blockIdx.x & 7;
    const int q0 = blockIdx.y * 128;

    int kmax;
    if (per_row) {
        int v = (tid < 128) ? vlp[b * T_ + q0 + tid] : 0;
#pragma unroll
        for (int off = 16; off; off >>= 1)
            v = max(v, __shfl_xor_sync(0xffffffffu, v, off));
        if (lane == 0) sred[w] = v;
        __syncthreads();
        kmax = sred[0];
#pragma unroll
        for (int i = 1; i < 8; i++) kmax = max(kmax, sred[i]);
    } else {
        kmax = vlp[b];
    }
    const int nkt = (kmax + 63) >> 6;

    int vl0, vl1;
    if (per_row) {
        vl0 = vlp[b * T_ + q0 + w * 16 + g];
        vl1 = vlp[b * T_ + q0 + w * 16 + g + 8];
    } else {
        vl0 = vl1 = kmax;
    }

    PDL_WAIT();

    const __half* qp = Q + (size_t)(b * T_ + q0) * qs + h * 64;
    for (int i = tid; i < 1024; i += 256) {
        const int r = i >> 3, ch = i & 7;
        *(uint4*)(cQ + r * AROWB + ch * 16) =
            *(const uint4*)(qp + (size_t)r * qs + ch * 8);
    }

    auto load_kv = [&](int kt, int stg) {
        const size_t kb = (size_t)(b * T_ + kt * 64) * kvs + h * 64;
        const uint32_t sb = uKV + stg * KV_STAGE;
        for (int i = tid; i < 512; i += 256) {
            const int r = i >> 3, ch = i & 7;
            const size_t go = kb + (size_t)r * kvs + ch * 8;
            const uint32_t so = r * AROWB + ch * 16;
            CP_ASYNC16(sb + so,        K + go);
            CP_ASYNC16(sb + 9216 + so, V + go);
        }
        CP_COMMIT();
    };
    load_kv(0, 0);

    float m0 = -1e30f, m1 = -1e30f, l0 = 0.f, l1 = 0.f;
    float o[8][4];
#pragma unroll
    for (int j = 0; j < 8; j++)
#pragma unroll
        for (int e = 0; e < 4; e++) o[j][e] = 0.f;

    const uint32_t qaddr = (w * 16 + (lane & 15)) * AROWB + (lane >> 4) * 16;
    const int bRow = (lane & 7) + ((lane >> 4) << 3);
    const int bK8  = ((lane >> 3) & 1) * 16;
    const int vRow = (lane & 7) + ((lane >> 3) & 1) * 8;
    const int vColB = (lane >> 4) * 16;

    for (int kt = 0; kt < nkt; kt++) {
        __syncthreads();
        if (kt + 1 < nkt) {
            load_kv(kt + 1, (kt + 1) & 1);
            CP_WAIT(1);
        } else {
            CP_WAIT(0);
        }
        __syncthreads();

        const uint32_t sK = uKV + (kt & 1) * KV_STAGE;
        const uint32_t uK = sK, uV = sK + 9216;

        float s[8][4];
#pragma unroll
        for (int j = 0; j < 8; j++)
#pragma unroll
            for (int e = 0; e < 4; e++) s[j][e] = 0.f;

#pragma unroll
        for (int kk = 0; kk < 4; kk++) {
            uint32_t a0, a1, a2, a3;
            LDMATRIX_X4(a0, a1, a2, a3, uQ + qaddr + kk * 32);
#pragma unroll
            for (int j2 = 0; j2 < 4; j2++) {
                uint32_t r0, r1, r2, r3;
                LDMATRIX_X4(r0, r1, r2, r3,
                            uK + (j2 * 16 + bRow) * AROWB + kk * 32 + bK8);
                MMA_F16(s[2*j2][0], s[2*j2][1], s[2*j2][2], s[2*j2][3],
                        a0, a1, a2, a3, r0, r1);
                MMA_F16(s[2*j2+1][0], s[2*j2+1][1], s[2*j2+1][2], s[2*j2+1][3],
                        a0, a1, a2, a3, r2, r3);
            }
        }

        const int kof = kt * 64 + c * 2;
        float mx0 = -1e30f, mx1 = -1e30f;
#pragma unroll
        for (int j = 0; j < 8; j++) {
            const int ki = kof + j * 8;
            s[j][0] = (ki     < vl0) ? s[j][0] * 0.125f : -1e10f;
            s[j][1] = (ki + 1 < vl0) ? s[j][1] * 0.125f : -1e10f;
            s[j][2] = (ki     < vl1) ? s[j][2] * 0.125f : -1e10f;
            s[j][3] = (ki + 1 < vl1) ? s[j][3] * 0.125f : -1e10f;
            mx0 = fmaxf(mx0, fmaxf(s[j][0], s[j][1]));
            mx1 = fmaxf(mx1, fmaxf(s[j][2], s[j][3]));
        }
        mx0 = fmaxf(mx0, __shfl_xor_sync(0xffffffffu, mx0, 1));
        mx0 = fmaxf(mx0, __shfl_xor_sync(0xffffffffu, mx0, 2));
        mx1 = fmaxf(mx1, __shfl_xor_sync(0xffffffffu, mx1, 1));
        mx1 = fmaxf(mx1, __shfl_xor_sync(0xffffffffu, mx1, 2));

        const float mn0 = fmaxf(m0, mx0), mn1 = fmaxf(m1, mx1);
        const float al_0 = __expf(m0 - mn0), al_1 = __expf(m1 - mn1);
        m0 = mn0; m1 = mn1;

        float rs0 = 0.f, rs1 = 0.f;
#pragma unroll
        for (int j = 0; j < 8; j++) {
            s[j][0] = __expf(s[j][0] - mn0);
            s[j][1] = __expf(s[j][1] - mn0);
            s[j][2] = __expf(s[j][2] - mn1);
            s[j][3] = __expf(s[j][3] - mn1);
            rs0 += s[j][0] + s[j][1];
            rs1 += s[j][2] + s[j][3];
        }
        rs0 += __shfl_xor_sync(0xffffffffu, rs0, 1);
        rs0 += __shfl_xor_sync(0xffffffffu, rs0, 2);
        rs1 += __shfl_xor_sync(0xffffffffu, rs1, 1);
        rs1 += __shfl_xor_sync(0xffffffffu, rs1, 2);
        l0 = l0 * al_0 + rs0;
        l1 = l1 * al_1 + rs1;

#pragma unroll
        for (int j = 0; j < 8; j++) {
            o[j][0] *= al_0; o[j][1] *= al_0;
            o[j][2] *= al_1; o[j][3] *= al_1;
        }

#pragma unroll
        for (int t = 0; t < 4; t++) {
            uint32_t p[4];
            p[0] = packh2(s[2*t][0],   s[2*t][1]);
            p[1] = packh2(s[2*t][2],   s[2*t][3]);
            p[2] = packh2(s[2*t+1][0], s[2*t+1][1]);
            p[3] = packh2(s[2*t+1][2], s[2*t+1][3]);
#pragma unroll
            for (int j2 = 0; j2 < 4; j2++) {
                uint32_t r0, r1, r2, r3;
                LDMATRIX_X4_T(r0, r1, r2, r3,
                              uV + (t * 16 + vRow) * AROWB + j2 * 32 + vColB);
                MMA_F16(o[2*j2][0], o[2*j2][1], o[2*j2][2], o[2*j2][3],
                        p[0], p[1], p[2], p[3], r0, r1);
                MMA_F16(o[2*j2+1][0], o[2*j2+1][1], o[2*j2+1][2], o[2*j2+1][3],
                        p[0], p[1], p[2], p[3], r2, r3);
            }
        }
    }

    const float il0 = 1.0f / l0, il1 = 1.0f / l1;
    const int r0g = b * T_ + q0 + w * 16 + g;
    const int r1g = r0g + 8;
#pragma unroll
    for (int j = 0; j < 8; j++) {
        const int col = h * 64 + j * 8 + c * 2;
        *(uint32_t*)&O[(size_t)r0g * D_ + col] = packh2(o[j][0] * il0, o[j][1] * il0);
        *(uint32_t*)&O[(size_t)r1g * D_ + col] = packh2(o[j][2] * il1, o[j][3] * il1);
    }
}

// ---------------------------------------------------------------------------
// out = LayerNorm(A + Bt) * g + be ; Bt is fp16. CONV=1 also emits fp16.
// ---------------------------------------------------------------------------
template <int CONV>
__global__ void __launch_bounds__(128)
addnorm_kernel(const float* __restrict__ A, const __half* __restrict__ Bt,
               const float* __restrict__ g, const float* __restrict__ be,
               float* __restrict__ out, __half* __restrict__ oh)
{
    PDL_TRIGGER();
    PDL_WAIT();
    const int row = blockIdx.x;
    const int tid = threadIdx.x;
    const size_t base = (size_t)row * D_;

    float4 a = *(const float4*)&A[base + tid * 4];
    const __half2* bp = (const __half2*)&Bt[base + tid * 4];
    float2 b01 = __half22float2(bp[0]);
    float2 b23 = __half22float2(bp[1]);
    float4 x = make_float4(a.x + b01.x, a.y + b01.y, a.z + b23.x, a.w + b23.y);

    float s  = x.x + x.y + x.z + x.w;
    float sq = x.x * x.x + x.y * x.y + x.z * x.z + x.w * x.w;
#pragma unroll
    for (int off = 16; off; off >>= 1) {
        s  += __shfl_xor_sync(0xffffffffu, s,  off);
        sq += __shfl_xor_sync(0xffffffffu, sq, off);
    }
    __shared__ float ss[4], ssq[4];
    if ((tid & 31) == 0) { ss[tid >> 5] = s; ssq[tid >> 5] = sq; }
    __syncthreads();
    s  = ss[0] + ss[1] + ss[2] + ss[3];
    sq = ssq[0] + ssq[1] + ssq[2] + ssq[3];

    float mu  = s * (1.0f / D_);
    float var = sq * (1.0f / D_) - mu * mu;
    float inv = rsqrtf(var + 1e-5f);

    float4 gg = *(const float4*)&g[tid * 4];
    float4 bb = *(const float4*)&be[tid * 4];
    float4 oo = make_float4((x.x - mu) * inv * gg.x + bb.x,
                            (x.y - mu) * inv * gg.y + bb.y,
                            (x.z - mu) * inv * gg.z + bb.z,
                            (x.w - mu) * inv * gg.w + bb.w);
    *(float4*)&out[base + tid * 4] = oo;
    if (CONV) {
        uint32_t* hp = (uint32_t*)&oh[base + tid * 4];
        hp[0] = packh2(oo.x, oo.y);
        hp[1] = packh2(oo.z, oo.w);
    }
}

// ---------------------------------------------------------------------------
// PDL launch helper
// ---------------------------------------------------------------------------
template <typename... ExpT, typename... ActT>
static void launch_pdl(void (*kern)(ExpT...), dim3 gr, dim3 bl, size_t shm,
                       ActT... args)
{
    cudaLaunchConfig_t cfg = {};
    cfg.gridDim = gr;
    cfg.blockDim = bl;
    cfg.dynamicSmemBytes = shm;
    cfg.stream = 0;
    cudaLaunchAttribute at[1];
    at[0].id = cudaLaunchAttributeProgrammaticStreamSerialization;
    at[0].val.programmaticStreamSerializationAllowed = 1;
    cfg.attrs = at;
    cfg.numAttrs = 1;
    cudaLaunchKernelEx(&cfg, kern, args...);
}

// ---------------------------------------------------------------------------
// Launch
// ---------------------------------------------------------------------------
extern "C" void kernel_launch(void* const* d_in, const int* in_sizes, int n_in,
                              void* d_out, int out_size)
{
    const float* X    = (const float*)d_in[0];
    const float* ENC  = (const float*)d_in[1];
    const int*   DVL  = (const int*)d_in[2];
    const int*   EVL  = (const int*)d_in[3];
    const float* Wmat[8] = {
        (const float*)d_in[4],  (const float*)d_in[5],
        (const float*)d_in[6],  (const float*)d_in[7],
        (const float*)d_in[8],  (const float*)d_in[9],
        (const float*)d_in[10], (const float*)d_in[11]};
    const float* W1   = (const float*)d_in[12];
    const float* b1   = (const float*)d_in[13];
    const float* W2   = (const float*)d_in[14];
    const float* b2   = (const float*)d_in[15];
    const float* G1   = (const float*)d_in[16];
    const float* BE1  = (const float*)d_in[17];
    const float* G2   = (const float*)d_in[18];
    const float* BE2  = (const float*)d_in[19];
    const float* G3   = (const float*)d_in[20];
    const float* BE3  = (const float*)d_in[21];
    float* out = (float*)d_out;

    float *Y, *Z;
    __half *tmph, *x1, *x2, *qkv, *kv, *q2, *at, *Fb, *Wb;
    cudaGetSymbolAddress((void**)&Y,    g_Y);
    cudaGetSymbolAddress((void**)&Z,    g_Z);
    cudaGetSymbolAddress((void**)&tmph, g_tmph);
    cudaGetSymbolAddress((void**)&x1,   g_x1);
    cudaGetSymbolAddress((void**)&x2,   g_x2);
    cudaGetSymbolAddress((void**)&qkv,  g_qkv);
    cudaGetSymbolAddress((void**)&kv,   g_kv);
    cudaGetSymbolAddress((void**)&q2,   g_q2);
    cudaGetSymbolAddress((void**)&at,   g_at);
    cudaGetSymbolAddress((void**)&Fb,   g_F);
    cudaGetSymbolAddress((void**)&Wb,   g_W);

    cudaFuncSetAttribute(attn_hmma,
                         cudaFuncAttributeMaxDynamicSharedMemorySize, ATT_SMEM);
    cudaFuncSetAttribute(gemm_hmma<0, 0>,
                         cudaFuncAttributeMaxDynamicSharedMemorySize, GEMM_SMEM);
    cudaFuncSetAttribute(gemm_hmma<1, 1>,
                         cudaFuncAttributeMaxDynamicSharedMemorySize, GEMM_SMEM);
    cudaFuncSetAttribute(gemm_hmma<1, 0>,
                         cudaFuncAttributeMaxDynamicSharedMemorySize, GEMM_SMEM);
    cudaFuncSetAttribute(gemm_dual,
                         cudaFuncAttributeMaxDynamicSharedMemorySize, GEMM_SMEM);

    size_t WO[10];
    for (int i = 0; i < 8; i++) WO[i] = (size_t)i * D_ * D_;
    WO[8] = 8ull * D_ * D_;
    WO[9] = WO[8] + (size_t)F_ * D_;

    const int nDD = D_ * D_ / 4;       // 65536
    const int nMD = M_ * D_ / 4;       // 2097152
    const int nFD = F_ * D_ / 4;       // 262144

    ConvSegs segs;
    int total4 = 0;
    for (int i = 0; i < 8; i++) {
        segs.src[i] = Wmat[i];
        segs.dst[i] = Wb + WO[i];
        segs.n4[i] = nDD; total4 += nDD;
    }
    segs.src[8] = W1; segs.dst[8] = Wb + WO[8]; segs.n4[8] = nFD; total4 += nFD;
    segs.src[9] = W2; segs.dst[9] = Wb + WO[9]; segs.n4[9] = nFD; total4 += nFD;
    segs.src[10] = X;   segs.dst[10] = x1; segs.n4[10] = nMD; total4 += nMD;
    segs.src[11] = ENC; segs.dst[11] = x2; segs.n4[11] = nMD; total4 += nMD;
    launch_pdl(mconv_kernel, dim3((total4 + 255) / 256), dim3(256), 0, segs);

    dim3 gQKV(1536 / 128, M_ / 128);   // (12, 128)
    dim3 gDUO(12,         M_ / 128);   // q2(4) + kv(8)
    dim3 gP  (D_ / 128,   M_ / 128);   // (4, 128)
    dim3 gF1 (F_ / 128,   M_ / 128);   // (16, 128)
    dim3 gA  (B_ * H_,    T_ / 128);   // (256, 4)
    dim3 gAN (M_);

    // ---- self-attention ----
    launch_pdl(gemm_hmma<0,0>, gQKV, dim3(128), GEMM_SMEM,
               (const __half*)x1, (const __half*)(Wb + WO[0]),
               (const float*)nullptr, qkv, 1536, D_);
    launch_pdl(attn_hmma, gA, dim3(256), (size_t)ATT_SMEM,
               (const __half*)qkv, 1536,
               (const __half*)(qkv + 512), (const __half*)(qkv + 1024), 1536,
               DVL, 1, at);
    launch_pdl(gemm_hmma<0,0>, gP, dim3(128), GEMM_SMEM,
               (const __half*)at, (const __half*)(Wb + WO[3]),
               (const float*)nullptr, tmph, D_, D_);
    launch_pdl(addnorm_kernel<1>, gAN, dim3(128), 0,
               X, (const __half*)tmph, G1, BE1, Y, x1);

    // ---- cross-attention (Q2 + KV in one launch) ----
    launch_pdl(gemm_dual, gDUO, dim3(128), GEMM_SMEM,
               (const __half*)x1, (const __half*)(Wb + WO[4]), q2, 512, 4,
               (const __half*)x2, (const __half*)(Wb + WO[5]), kv, 1024, D_);
    launch_pdl(attn_hmma, gA, dim3(256), (size_t)ATT_SMEM,
               (const __half*)q2, D_,
               (const __half*)kv, (const __half*)(kv + 512), 1024,
               EVL, 0, at);
    launch_pdl(gemm_hmma<0,0>, gP, dim3(128), GEMM_SMEM,
               (const __half*)at, (const __half*)(Wb + WO[7]),
               (const float*)nullptr, tmph, D_, D_);
    launch_pdl(addnorm_kernel<1>, gAN, dim3(128), 0,
               (const float*)Y, (const __half*)tmph, G2, BE2, Z, x2);

    // ---- FFN ----
    launch_pdl(gemm_hmma<1,1>, gF1, dim3(128), GEMM_SMEM,
               (const __half*)x2, (const __half*)(Wb + WO[8]),
               b1, Fb, F_, D_);
    launch_pdl(gemm_hmma<1,0>, gP, dim3(128), GEMM_SMEM,
               (const __half*)Fb, (const __half*)(Wb + WO[9]),
               b2, tmph, D_, F_);
    launch_pdl(addnorm_kernel<0>, gAN, dim3(128), 0,
               (const float*)Z, (const __half*)tmph, G3, BE3, out,
               (__half*)nullptr);
}